// round 3
// baseline (speedup 1.0000x reference)
#include <cuda_runtime.h>
#include <math.h>

#define CAP 192

// ---------------- static device scratch (no allocation allowed) ----------------
__device__ float g_A0[(size_t)4096*4096];
__device__ float g_Aaug[(size_t)4096*4096];
__device__ float g_As1[(size_t)2048*2048];
__device__ float g_As2[(size_t)1024*1024];
__device__ float g_As3[(size_t)512*512];
__device__ float g_A4[(size_t)256*256];
__device__ float g_x0[4096*32];
__device__ float g_x1[2048*64];
__device__ float g_x2[1024*128];
__device__ float g_x3[512*256];
__device__ float g_x4[256*512];
__device__ float g_xg[2048*64];
__device__ float g_xu[4096*64];
__device__ float g_xcat[4096*64];
__device__ float g_bY[4096*64];
__device__ float g_bU[4096*64];
__device__ float g_bZ[4096*64];
__device__ float g_dinv[4096];
__device__ float g_fill[4096];
__device__ float g_score[4096];
__device__ float g_vals[4096];
__device__ float g_wn[1];
__device__ int   g_perm0[2048];
__device__ int   g_perm1[1024];
__device__ int   g_perm2[512];
__device__ int   g_perm3[256];
__device__ int   g_cnt[4096];
__device__ int   g_bucket[4096*CAP];

// ---------------- kernels ----------------

__global__ void k_scatter_edges(const int* __restrict__ e, int E, float* A, int n){
    int i = blockIdx.x*blockDim.x + threadIdx.x;
    if (i >= E) return;
    int s = e[i], d = e[E+i];
    atomicAdd(&A[(size_t)d*n + s], 1.0f);
}

__global__ void k_bucket_fill(const int* __restrict__ e, int E, int* cnt, int* bucket){
    int i = blockIdx.x*blockDim.x + threadIdx.x;
    if (i >= E) return;
    int s = e[i], d = e[E+i];
    if (s == d) return;
    int p = atomicAdd(&cnt[s], 1);
    if (p < CAP) bucket[s*CAP + p] = d;
}

// A2 = 2*offdiag(A0), diag = 0   (the 2*Aoff term of (Aoff+I)^2 minus diag)
__global__ void k_aug0_init(const float* __restrict__ A0, float* A2, int n){
    size_t idx = (size_t)blockIdx.x*blockDim.x + threadIdx.x;
    size_t tot = (size_t)n*n;
    if (idx >= tot) return;
    int i = (int)(idx / n), j = (int)(idx % n);
    A2[idx] = (i == j) ? 0.0f : 2.0f*A0[idx];
}

// A2 += offdiag(Aoff^2) via edge self-join on e1.src == e2.dst
__global__ void k_aug0_join(const int* __restrict__ e, int E, const int* __restrict__ cnt,
                            const int* __restrict__ bucket, float* A2, int n){
    int i = blockIdx.x*blockDim.x + threadIdx.x;
    if (i >= E) return;
    int s2 = e[i], d2 = e[E+i];
    if (s2 == d2) return;
    int c = min(cnt[d2], CAP);
    const int* b = bucket + d2*CAP;
    for (int t = 0; t < c; t++){
        int d1 = b[t];
        if (d1 != s2) atomicAdd(&A2[(size_t)d1*n + s2], 1.0f);
    }
}

// deg = rowsum(A) + fill (fill=2 where diag==0); dinv = 1/sqrt(deg)
__global__ void k_deg(const float* __restrict__ A, int n, float* dinv, float* fill){
    int row  = blockIdx.x*(blockDim.x >> 5) + (threadIdx.x >> 5);
    int lane = threadIdx.x & 31;
    if (row >= n) return;
    const float* r = A + (size_t)row*n;
    float s = 0.f;
    for (int j = lane; j < n; j += 32) s += r[j];
    #pragma unroll
    for (int o = 16; o; o >>= 1) s += __shfl_xor_sync(0xffffffffu, s, o);
    if (lane == 0){
        float f = (r[row] == 0.0f) ? 2.0f : 0.0f;
        float deg = s + f;
        dinv[row] = (deg > 0.f) ? 1.0f/sqrtf(deg) : 0.0f;
        fill[row] = f;
    }
}

// generic tiled SGEMM: C = A@B. flags: 1 = A diag->1, 2 = B diag->1, 4 = zero C diag
__global__ __launch_bounds__(256) void k_sgemm(const float* A, const float* B,
                                               float* __restrict__ C,
                                               int M, int N, int K, int flags){
    __shared__ float As[16][68];
    __shared__ float Bs[16][64];
    int tid = threadIdx.x;
    int tx = tid & 15, ty = tid >> 4;
    int bm = blockIdx.y*64, bn = blockIdx.x*64;
    float acc[4][4] = {};
    for (int kb = 0; kb < K; kb += 16){
        int kk = tid & 15, mb = tid >> 4;
        #pragma unroll
        for (int r = 0; r < 4; r++){
            int m = mb + r*16;
            int gm = bm + m, gk = kb + kk;
            float v = 0.f;
            if (gm < M && gk < K){
                v = A[(size_t)gm*K + gk];
                if ((flags & 1) && gm == gk) v = 1.0f;
            }
            As[kk][m] = v;
        }
        int nn = tid & 63, kb2 = tid >> 6;
        #pragma unroll
        for (int r = 0; r < 4; r++){
            int k2 = kb2 + r*4;
            int gk = kb + k2, gn = bn + nn;
            float v = 0.f;
            if (gk < K && gn < N){
                v = B[(size_t)gk*N + gn];
                if ((flags & 2) && gk == gn) v = 1.0f;
            }
            Bs[k2][nn] = v;
        }
        __syncthreads();
        #pragma unroll
        for (int k = 0; k < 16; k++){
            float a[4], b[4];
            #pragma unroll
            for (int i2 = 0; i2 < 4; i2++) a[i2] = As[k][ty*4 + i2];
            #pragma unroll
            for (int j2 = 0; j2 < 4; j2++) b[j2] = Bs[k][tx*4 + j2];
            #pragma unroll
            for (int i2 = 0; i2 < 4; i2++)
                #pragma unroll
                for (int j2 = 0; j2 < 4; j2++)
                    acc[i2][j2] += a[i2]*b[j2];
        }
        __syncthreads();
    }
    #pragma unroll
    for (int i2 = 0; i2 < 4; i2++){
        int gm = bm + ty*4 + i2;
        if (gm >= M) continue;
        #pragma unroll
        for (int j2 = 0; j2 < 4; j2++){
            int gn = bn + tx*4 + j2;
            if (gn >= N) continue;
            float v = acc[i2][j2];
            if ((flags & 4) && gm == gn) v = 0.f;
            C[(size_t)gm*N + gn] = v;
        }
    }
}

__global__ void k_scale_rows(const float* Y, const float* dinv, float* U, int n, int F){
    int idx = blockIdx.x*blockDim.x + threadIdx.x;
    if (idx >= n*F) return;
    U[idx] = dinv[idx / F] * Y[idx];
}

__global__ void k_gcn_epi(const float* Z, const float* U, const float* dinv, const float* fill,
                          const float* __restrict__ b, float* out, int n, int F, int relu){
    int idx = blockIdx.x*blockDim.x + threadIdx.x;
    if (idx >= n*F) return;
    int i = idx / F, f = idx % F;
    float v = dinv[i]*(Z[idx] + fill[i]*U[idx]) + b[f];
    if (relu) v = fmaxf(v, 0.f);
    out[idx] = v;
}

__global__ void k_wnorm(const float* w, int F, float* out){
    __shared__ float sh[256];
    float s = 0.f;
    for (int i = threadIdx.x; i < F; i += 256) s += w[i]*w[i];
    sh[threadIdx.x] = s; __syncthreads();
    for (int o = 128; o; o >>= 1){
        if (threadIdx.x < o) sh[threadIdx.x] += sh[threadIdx.x + o];
        __syncthreads();
    }
    if (threadIdx.x == 0) out[0] = sqrtf(sh[0]);
}

__global__ void k_score(const float* x, int n, int F, const float* __restrict__ w,
                        const float* nrm, float* score){
    int i = blockIdx.x*blockDim.x + threadIdx.x;
    if (i >= n) return;
    const float* r = x + (size_t)i*F;
    float s = 0.f;
    for (int f = 0; f < F; f++) s += r[f]*w[f];
    score[i] = tanhf(s / nrm[0]);
}

// stable top-k by exact ranking: matches jax.lax.top_k ordering
__global__ void k_topk(const float* __restrict__ s, int n, int k, int* idx, float* vals){
    int i = blockIdx.x*blockDim.x + threadIdx.x;
    if (i >= n) return;
    float si = s[i];
    int c = 0;
    for (int j = 0; j < n; j++){
        float sj = s[j];
        c += (sj > si) || (sj == si && j < i);
    }
    if (c < k){ idx[c] = i; vals[c] = si; }
}

__global__ void k_gather_x(const float* x, int F, const int* idx, const float* vals,
                           float* out, int k){
    int t = blockIdx.x*blockDim.x + threadIdx.x;
    if (t >= k*F) return;
    int r = t / F, f = t % F;
    out[t] = x[(size_t)idx[r]*F + f] * vals[r];
}

__global__ void k_gather_A(const float* A, int n, const int* __restrict__ idx, float* out, int k){
    size_t t = (size_t)blockIdx.x*blockDim.x + threadIdx.x;
    if (t >= (size_t)k*k) return;
    int r = (int)(t / k), c = (int)(t % k);
    out[t] = A[(size_t)idx[r]*n + idx[c]];
}

__global__ void k_concat_res(const float* res, int C, float* xcat, int n){
    int t = blockIdx.x*blockDim.x + threadIdx.x;
    int W = 2*C;
    if (t >= n*W) return;
    int r = t / W, f = t % W;
    xcat[t] = (f < C) ? res[(size_t)r*C + f] : 0.f;
}

__global__ void k_scatter_up(const float* x, int Fx, int C, const int* perm,
                             float* xcat, int nsmall){
    int t = blockIdx.x*blockDim.x + threadIdx.x;
    if (t >= nsmall*C) return;
    int r = t / C, f = t % C;
    xcat[(size_t)perm[r]*(2*C) + C + f] = x[(size_t)r*Fx + f];
}

__global__ void k_softmax(const float* z, float* out, int n, int C){
    int i = blockIdx.x*blockDim.x + threadIdx.x;
    if (i >= n) return;
    const float* r = z + (size_t)i*C;
    float m = -1e30f;
    for (int c = 0; c < C; c++) m = fmaxf(m, r[c]);
    float s = 0.f;
    for (int c = 0; c < C; c++) s += expf(r[c] - m);
    float inv = 1.0f/s;
    for (int c = 0; c < C; c++) out[(size_t)i*C + c] = expf(r[c] - m)*inv;
}

// ---------------- host orchestration ----------------

extern "C" void kernel_launch(void* const* d_in, const int* in_sizes, int n_in,
                              void* d_out, int out_size){
    const float* x_in = (const float*)d_in[0];
    const int*   eidx = (const int*)d_in[1];
    const float *Wd[5], *bd[5], *pv[4], *Wu[4], *bu[4];
    for (int i = 0; i < 5; i++){ Wd[i] = (const float*)d_in[2 + 2*i]; bd[i] = (const float*)d_in[3 + 2*i]; }
    for (int i = 0; i < 4; i++)  pv[i] = (const float*)d_in[12 + i];
    for (int i = 0; i < 4; i++){ Wu[i] = (const float*)d_in[16 + 2*i]; bu[i] = (const float*)d_in[17 + 2*i]; }
    const float* Wo = (const float*)d_in[24];
    const float* bo = (const float*)d_in[25];
    int E = in_sizes[1] / 2;

    float *pA0,*pAaug,*pAs1,*pAs2,*pAs3,*pA4;
    float *px0,*px1,*px2,*px3,*px4,*pxg,*pxu,*pxcat;
    float *pY,*pU,*pZ,*pdinv,*pfill,*pscore,*pvals,*pwn;
    int *pperm0,*pperm1,*pperm2,*pperm3,*pcnt,*pbucket;
    cudaGetSymbolAddress((void**)&pA0,   g_A0);
    cudaGetSymbolAddress((void**)&pAaug, g_Aaug);
    cudaGetSymbolAddress((void**)&pAs1,  g_As1);
    cudaGetSymbolAddress((void**)&pAs2,  g_As2);
    cudaGetSymbolAddress((void**)&pAs3,  g_As3);
    cudaGetSymbolAddress((void**)&pA4,   g_A4);
    cudaGetSymbolAddress((void**)&px0,   g_x0);
    cudaGetSymbolAddress((void**)&px1,   g_x1);
    cudaGetSymbolAddress((void**)&px2,   g_x2);
    cudaGetSymbolAddress((void**)&px3,   g_x3);
    cudaGetSymbolAddress((void**)&px4,   g_x4);
    cudaGetSymbolAddress((void**)&pxg,   g_xg);
    cudaGetSymbolAddress((void**)&pxu,   g_xu);
    cudaGetSymbolAddress((void**)&pxcat, g_xcat);
    cudaGetSymbolAddress((void**)&pY,    g_bY);
    cudaGetSymbolAddress((void**)&pU,    g_bU);
    cudaGetSymbolAddress((void**)&pZ,    g_bZ);
    cudaGetSymbolAddress((void**)&pdinv, g_dinv);
    cudaGetSymbolAddress((void**)&pfill, g_fill);
    cudaGetSymbolAddress((void**)&pscore,g_score);
    cudaGetSymbolAddress((void**)&pvals, g_vals);
    cudaGetSymbolAddress((void**)&pwn,   g_wn);
    cudaGetSymbolAddress((void**)&pperm0,g_perm0);
    cudaGetSymbolAddress((void**)&pperm1,g_perm1);
    cudaGetSymbolAddress((void**)&pperm2,g_perm2);
    cudaGetSymbolAddress((void**)&pperm3,g_perm3);
    cudaGetSymbolAddress((void**)&pcnt,  g_cnt);
    cudaGetSymbolAddress((void**)&pbucket,g_bucket);

    auto gemm = [&](const float* A, const float* B, float* C, int M, int N, int K, int flags){
        dim3 g((N + 63)/64, (M + 63)/64);
        k_sgemm<<<g, 256>>>(A, B, C, M, N, K, flags);
    };
    auto gcn = [&](const float* A, int n, const float* x, int fin, const float* W, const float* b,
                   int fout, float* out, bool relu){
        k_deg<<<(n + 7)/8, 256>>>(A, n, pdinv, pfill);
        gemm(x, W, pY, n, fout, fin, 0);
        int tot = n*fout;
        k_scale_rows<<<(tot + 255)/256, 256>>>(pY, pdinv, pU, n, fout);
        gemm(A, pU, pZ, n, fout, n, 0);
        k_gcn_epi<<<(tot + 255)/256, 256>>>(pZ, pU, pdinv, pfill, b, out, n, fout, relu ? 1 : 0);
    };
    auto topk = [&](const float* x, int n, int F, const float* w, int k, int* perm){
        k_wnorm<<<1, 256>>>(w, F, pwn);
        k_score<<<(n + 255)/256, 256>>>(x, n, F, w, pwn, pscore);
        k_topk<<<(n + 255)/256, 256>>>(pscore, n, k, perm, pvals);
    };

    // ---- build A0 (4096x4096) from edge list ----
    cudaMemsetAsync(pA0, 0, (size_t)4096*4096*sizeof(float), 0);
    k_scatter_edges<<<(E + 255)/256, 256>>>(eidx, E, pA0, 4096);

    // ---- down level 0 ----
    gcn(pA0, 4096, x_in, 128, Wd[0], bd[0], 32, px0, true);

    // ---- level 1: sparse augment at 4096, pool to 2048 ----
    cudaMemsetAsync(pcnt, 0, 4096*sizeof(int), 0);
    k_bucket_fill<<<(E + 255)/256, 256>>>(eidx, E, pcnt, pbucket);
    {
        size_t tot = (size_t)4096*4096;
        k_aug0_init<<<(unsigned)((tot + 255)/256), 256>>>(pA0, pAaug, 4096);
    }
    k_aug0_join<<<(E + 255)/256, 256>>>(eidx, E, pcnt, pbucket, pAaug, 4096);
    topk(px0, 4096, 32, pv[0], 2048, pperm0);
    k_gather_x<<<(2048*32 + 255)/256, 256>>>(px0, 32, pperm0, pvals, pxg, 2048);
    k_gather_A<<<(unsigned)(((size_t)2048*2048 + 255)/256), 256>>>(pAaug, 4096, pperm0, pAs1, 2048);
    gcn(pAs1, 2048, pxg, 32, Wd[1], bd[1], 64, px1, true);

    // ---- level 2: dense augment at 2048, pool to 1024 ----
    gemm(pAs1, pAs1, pAaug, 2048, 2048, 2048, 1 | 2 | 4);
    topk(px1, 2048, 64, pv[1], 1024, pperm1);
    k_gather_x<<<(1024*64 + 255)/256, 256>>>(px1, 64, pperm1, pvals, pxg, 1024);
    k_gather_A<<<(unsigned)(((size_t)1024*1024 + 255)/256), 256>>>(pAaug, 2048, pperm1, pAs2, 1024);
    gcn(pAs2, 1024, pxg, 64, Wd[2], bd[2], 128, px2, true);

    // ---- level 3: dense augment at 1024, pool to 512 ----
    gemm(pAs2, pAs2, pAaug, 1024, 1024, 1024, 1 | 2 | 4);
    topk(px2, 1024, 128, pv[2], 512, pperm2);
    k_gather_x<<<(512*128 + 255)/256, 256>>>(px2, 128, pperm2, pvals, pxg, 512);
    k_gather_A<<<(unsigned)(((size_t)512*512 + 255)/256), 256>>>(pAaug, 1024, pperm2, pAs3, 512);
    gcn(pAs3, 512, pxg, 128, Wd[3], bd[3], 256, px3, true);

    // ---- level 4: dense augment at 512, pool to 256 ----
    gemm(pAs3, pAs3, pAaug, 512, 512, 512, 1 | 2 | 4);
    topk(px3, 512, 256, pv[3], 256, pperm3);
    k_gather_x<<<(256*256 + 255)/256, 256>>>(px3, 256, pperm3, pvals, pxg, 256);
    k_gather_A<<<(unsigned)(((size_t)256*256 + 255)/256), 256>>>(pAaug, 512, pperm3, pA4, 256);
    gcn(pA4, 256, pxg, 256, Wd[4], bd[4], 512, px4, true);

    // ---- up path ----
    // up0: res=x3 (512x256), perm3, x4 (256x512), C=256 -> xcat 512x512
    k_concat_res<<<(512*512 + 255)/256, 256>>>(px3, 256, pxcat, 512);
    k_scatter_up<<<(256*256 + 255)/256, 256>>>(px4, 512, 256, pperm3, pxcat, 256);
    gcn(pAs3, 512, pxcat, 512, Wu[0], bu[0], 256, pxu, true);

    // up1: res=x2 (1024x128), perm2, xu (512x256), C=128 -> xcat 1024x256
    k_concat_res<<<(1024*256 + 255)/256, 256>>>(px2, 128, pxcat, 1024);
    k_scatter_up<<<(512*128 + 255)/256, 256>>>(pxu, 256, 128, pperm2, pxcat, 512);
    gcn(pAs2, 1024, pxcat, 256, Wu[1], bu[1], 128, pxu, true);

    // up2: res=x1 (2048x64), perm1, xu (1024x128), C=64 -> xcat 2048x128
    k_concat_res<<<(2048*128 + 255)/256, 256>>>(px1, 64, pxcat, 2048);
    k_scatter_up<<<(1024*64 + 255)/256, 256>>>(pxu, 128, 64, pperm1, pxcat, 1024);
    gcn(pAs1, 2048, pxcat, 128, Wu[2], bu[2], 64, pxu, true);

    // up3: res=x0 (4096x32), perm0, xu (2048x64), C=32 -> xcat 4096x64, NO relu
    k_concat_res<<<(4096*64 + 255)/256, 256>>>(px0, 32, pxcat, 4096);
    k_scatter_up<<<(2048*32 + 255)/256, 256>>>(pxu, 64, 32, pperm0, pxcat, 2048);
    gcn(pA0, 4096, pxcat, 64, Wu[3], bu[3], 32, pxu, false);

    // ---- final GCN + softmax ----
    gcn(pA0, 4096, pxu, 32, Wo, bo, 37, pxcat, false);
    k_softmax<<<(4096 + 255)/256, 256>>>(pxcat, (float*)d_out, 4096, 37);
}

// round 6
// speedup vs baseline: 1.9923x; 1.9923x over previous
#include <cuda_runtime.h>
#include <math.h>

#define CAP 192

// ---------------- static device scratch (no allocation allowed) ----------------
__device__ float g_Aaug[(size_t)4096*4096];
__device__ float g_As1[(size_t)2048*2048];
__device__ float g_As2[(size_t)1024*1024];
__device__ float g_As3[(size_t)512*512];
__device__ float g_A4[(size_t)256*256];
__device__ float g_x0[4096*32];
__device__ float g_x1[2048*64];
__device__ float g_x2[1024*128];
__device__ float g_x3[512*256];
__device__ float g_x4[256*512];
__device__ float g_xg[2048*64];
__device__ float g_xu[4096*64];
__device__ float g_xcat[4096*64];
__device__ float g_bU[4096*64];
__device__ float g_bZ[4096*64];
__device__ float g_dinv0[4096], g_fill0[4096];
__device__ float g_dinv1[2048], g_fill1[2048];
__device__ float g_dinv2[1024], g_fill2[1024];
__device__ float g_dinv3[512],  g_fill3[512];
__device__ float g_dinv4[256],  g_fill4[256];
__device__ float g_score[4096];
__device__ float g_vals[4096];
__device__ float g_wn[1];
__device__ int   g_perm0[2048];
__device__ int   g_perm1[1024];
__device__ int   g_perm2[512];
__device__ int   g_perm3[256];
__device__ int   g_cnt[4096];
__device__ int   g_degi[4096];
__device__ int   g_selfc[4096];
__device__ int   g_bucket[4096*CAP];

// ---------------- sparse level-0 kernels ----------------

__global__ void k_edge_stats(const int* __restrict__ e, int E, int* degi, int* selfc){
    int i = blockIdx.x*blockDim.x + threadIdx.x;
    if (i >= E) return;
    int s = e[i], d = e[E+i];
    atomicAdd(&degi[d], 1);
    if (s == d) atomicAdd(&selfc[d], 1);
}

__global__ void k_deg0_fin(const int* __restrict__ degi, const int* __restrict__ selfc,
                           float* dinv, float* fill, int n){
    int i = blockIdx.x*blockDim.x + threadIdx.x;
    if (i >= n) return;
    float f = (selfc[i] == 0) ? 2.0f : 0.0f;
    float deg = (float)degi[i] + f;
    dinv[i] = (deg > 0.f) ? 1.0f/sqrtf(deg) : 0.0f;
    fill[i] = f;
}

// Aaug += 2 on offdiag edges (the 2*Aoff term of (Aoff+I)^2 minus diag)
__global__ void k_scatter_aug(const int* __restrict__ e, int E, float* A, int n){
    int i = blockIdx.x*blockDim.x + threadIdx.x;
    if (i >= E) return;
    int s = e[i], d = e[E+i];
    if (s != d) atomicAdd(&A[(size_t)d*n + s], 2.0f);
}

__global__ void k_bucket_fill(const int* __restrict__ e, int E, int* cnt, int* bucket){
    int i = blockIdx.x*blockDim.x + threadIdx.x;
    if (i >= E) return;
    int s = e[i], d = e[E+i];
    if (s == d) return;
    int p = atomicAdd(&cnt[s], 1);
    if (p < CAP) bucket[s*CAP + p] = d;
}

// Aaug += offdiag(Aoff^2) via edge self-join
__global__ void k_aug0_join(const int* __restrict__ e, int E, const int* __restrict__ cnt,
                            const int* __restrict__ bucket, float* A2, int n){
    int i = blockIdx.x*blockDim.x + threadIdx.x;
    if (i >= E) return;
    int s2 = e[i], d2 = e[E+i];
    if (s2 == d2) return;
    int c = min(cnt[d2], CAP);
    const int* b = bucket + d2*CAP;
    for (int t = 0; t < c; t++){
        int d1 = b[t];
        if (d1 != s2) atomicAdd(&A2[(size_t)d1*n + s2], 1.0f);
    }
}

// Z[d][:] += U[s][:] per edge; warp-per-edge
__global__ void k_spmm(const int* __restrict__ e, int E, const float* __restrict__ U,
                       float* Z, int F){
    int w = (blockIdx.x*blockDim.x + threadIdx.x) >> 5;
    int lane = threadIdx.x & 31;
    if (w >= E) return;
    int s = e[w], d = e[E+w];
    const float* ur = U + (size_t)s*F;
    float* zr = Z + (size_t)d*F;
    for (int f = lane; f < F; f += 32) atomicAdd(&zr[f], ur[f]);
}

// ---------------- dense helpers ----------------

// deg = rowsum(A) + fill (fill=2 where diag==0); dinv = 1/sqrt(deg)
__global__ void k_deg(const float* __restrict__ A, int n, float* dinv, float* fill){
    int row  = blockIdx.x*(blockDim.x >> 5) + (threadIdx.x >> 5);
    int lane = threadIdx.x & 31;
    if (row >= n) return;
    const float* r = A + (size_t)row*n;
    float s = 0.f;
    for (int j = lane; j < n; j += 32) s += r[j];
    #pragma unroll
    for (int o = 16; o; o >>= 1) s += __shfl_xor_sync(0xffffffffu, s, o);
    if (lane == 0){
        float f = (r[row] == 0.0f) ? 2.0f : 0.0f;
        float deg = s + f;
        dinv[row] = (deg > 0.f) ? 1.0f/sqrtf(deg) : 0.0f;
        fill[row] = f;
    }
}

// Tiled SGEMM, BM=128, BK=8, TM=8, 256 threads; BN/TN templated (BN/TN==16).
// flags: 1 A diag->1, 2 B diag->1, 4 zero C diag,
//        8 epi: out=dinv[m]*acc, 16 epi: out=dinv[m]*(acc+fill[m]*U[m][n])+bias[n], 32 relu
template<int BN, int TN>
__global__ __launch_bounds__(256) void k_gemm(
    const float* __restrict__ A, const float* __restrict__ B, float* __restrict__ C,
    int M, int N, int K, int flags,
    const float* __restrict__ dinv, const float* __restrict__ fl,
    const float* __restrict__ bias, const float* __restrict__ Uin)
{
    const int BM = 128, BK = 8, TM = 8;
    __shared__ float As[BK][BM+4];
    __shared__ float Bs[BK][BN];
    int tid = threadIdx.x;
    int tx = tid % (BN/TN);
    int ty = tid / (BN/TN);
    int bm = blockIdx.y*BM, bn = blockIdx.x*BN;
    float acc[TM][TN] = {};
    int arow = tid >> 1, acol = (tid & 1)*4;
    const bool adiag = flags & 1, bdiag = flags & 2;

    for (int kb = 0; kb < K; kb += BK){
        // A tile (M%128==0, K%8==0 guaranteed by call sites)
        float4 av = *reinterpret_cast<const float4*>(&A[(size_t)(bm+arow)*K + kb + acol]);
        if (adiag){
            int gm = bm + arow, gk = kb + acol;
            if (gm >= gk && gm < gk + 4) (&av.x)[gm - gk] = 1.0f;
        }
        As[acol+0][arow] = av.x; As[acol+1][arow] = av.y;
        As[acol+2][arow] = av.z; As[acol+3][arow] = av.w;
        // B tile (scalar, N-guarded)
        #pragma unroll
        for (int t = 0; t < (BK*BN)/256; t++){
            int el = tid + t*256;
            int kr = el / BN, cc = el % BN;
            int gk = kb + kr, gn = bn + cc;
            float v = 0.f;
            if (gn < N){
                v = B[(size_t)gk*N + gn];
                if (bdiag && gk == gn) v = 1.0f;
            }
            Bs[kr][cc] = v;
        }
        __syncthreads();
        #pragma unroll
        for (int k = 0; k < BK; k++){
            float a[TM], b[TN];
            #pragma unroll
            for (int i = 0; i < TM; i++) a[i] = As[k][ty*TM + i];
            #pragma unroll
            for (int j = 0; j < TN; j++) b[j] = Bs[k][tx*TN + j];
            #pragma unroll
            for (int i = 0; i < TM; i++)
                #pragma unroll
                for (int j = 0; j < TN; j++)
                    acc[i][j] += a[i]*b[j];
        }
        __syncthreads();
    }

    const bool ediag0 = flags & 4, escale = flags & 8, egcn = flags & 16, erelu = flags & 32;
    #pragma unroll
    for (int i = 0; i < TM; i++){
        int gm = bm + ty*TM + i;
        float dv = (escale || egcn) ? dinv[gm] : 1.0f;
        float fv = egcn ? fl[gm] : 0.0f;
        #pragma unroll
        for (int j = 0; j < TN; j++){
            int gn = bn + tx*TN + j;
            if (gn >= N) continue;
            float v = acc[i][j];
            if (egcn)       v = dv*(v + fv*Uin[(size_t)gm*N + gn]) + bias[gn];
            else if (escale) v *= dv;
            if (erelu) v = fmaxf(v, 0.f);
            if (ediag0 && gm == gn) v = 0.f;
            C[(size_t)gm*N + gn] = v;
        }
    }
}

__global__ void k_gcn_epi(const float* Z, const float* U, const float* dinv, const float* fill,
                          const float* __restrict__ b, float* out, int n, int F, int relu){
    int idx = blockIdx.x*blockDim.x + threadIdx.x;
    if (idx >= n*F) return;
    int i = idx / F, f = idx % F;
    float v = dinv[i]*(Z[idx] + fill[i]*U[idx]) + b[f];
    if (relu) v = fmaxf(v, 0.f);
    out[idx] = v;
}

// ---------------- topk / gather / misc ----------------

__global__ void k_wnorm(const float* w, int F, float* out){
    __shared__ float sh[256];
    float s = 0.f;
    for (int i = threadIdx.x; i < F; i += 256) s += w[i]*w[i];
    sh[threadIdx.x] = s; __syncthreads();
    for (int o = 128; o; o >>= 1){
        if (threadIdx.x < o) sh[threadIdx.x] += sh[threadIdx.x + o];
        __syncthreads();
    }
    if (threadIdx.x == 0) out[0] = sqrtf(sh[0]);
}

__global__ void k_score(const float* x, int n, int F, const float* __restrict__ w,
                        const float* nrm, float* score){
    int i = blockIdx.x*blockDim.x + threadIdx.x;
    if (i >= n) return;
    const float* r = x + (size_t)i*F;
    float s = 0.f;
    for (int f = 0; f < F; f++) s += r[f]*w[f];
    score[i] = tanhf(s / nrm[0]);
}

// stable top-k by exact ranking: matches jax.lax.top_k ordering
__global__ void k_topk(const float* __restrict__ s, int n, int k, int* idx, float* vals){
    int i = blockIdx.x*blockDim.x + threadIdx.x;
    if (i >= n) return;
    float si = s[i];
    int c = 0;
    for (int j = 0; j < n; j++){
        float sj = s[j];
        c += (sj > si) || (sj == si && j < i);
    }
    if (c < k){ idx[c] = i; vals[c] = si; }
}

__global__ void k_gather_x(const float* x, int F, const int* idx, const float* vals,
                           float* out, int k){
    int t = blockIdx.x*blockDim.x + threadIdx.x;
    if (t >= k*F) return;
    int r = t / F, f = t % F;
    out[t] = x[(size_t)idx[r]*F + f] * vals[r];
}

__global__ void k_gather_A(const float* A, int n, const int* __restrict__ idx, float* out, int k){
    size_t t = (size_t)blockIdx.x*blockDim.x + threadIdx.x;
    if (t >= (size_t)k*k) return;
    int r = (int)(t / k), c = (int)(t % k);
    out[t] = A[(size_t)idx[r]*n + idx[c]];
}

__global__ void k_concat_res(const float* res, int C, float* xcat, int n){
    int t = blockIdx.x*blockDim.x + threadIdx.x;
    int W = 2*C;
    if (t >= n*W) return;
    int r = t / W, f = t % W;
    xcat[t] = (f < C) ? res[(size_t)r*C + f] : 0.f;
}

__global__ void k_scatter_up(const float* x, int Fx, int C, const int* perm,
                             float* xcat, int nsmall){
    int t = blockIdx.x*blockDim.x + threadIdx.x;
    if (t >= nsmall*C) return;
    int r = t / C, f = t % C;
    xcat[(size_t)perm[r]*(2*C) + C + f] = x[(size_t)r*Fx + f];
}

__global__ void k_softmax(const float* z, float* out, int n, int C){
    int i = blockIdx.x*blockDim.x + threadIdx.x;
    if (i >= n) return;
    const float* r = z + (size_t)i*C;
    float m = -1e30f;
    for (int c = 0; c < C; c++) m = fmaxf(m, r[c]);
    float s = 0.f;
    for (int c = 0; c < C; c++) s += expf(r[c] - m);
    float inv = 1.0f/s;
    for (int c = 0; c < C; c++) out[(size_t)i*C + c] = expf(r[c] - m)*inv;
}

// ---------------- host orchestration ----------------

extern "C" void kernel_launch(void* const* d_in, const int* in_sizes, int n_in,
                              void* d_out, int out_size){
    const float* x_in = (const float*)d_in[0];
    const int*   eidx = (const int*)d_in[1];
    const float *Wd[5], *bd[5], *pv[4], *Wu[4], *bu[4];
    for (int i = 0; i < 5; i++){ Wd[i] = (const float*)d_in[2 + 2*i]; bd[i] = (const float*)d_in[3 + 2*i]; }
    for (int i = 0; i < 4; i++)  pv[i] = (const float*)d_in[12 + i];
    for (int i = 0; i < 4; i++){ Wu[i] = (const float*)d_in[16 + 2*i]; bu[i] = (const float*)d_in[17 + 2*i]; }
    const float* Wo = (const float*)d_in[24];
    const float* bo = (const float*)d_in[25];
    int E = in_sizes[1] / 2;

    float *pAaug,*pAs1,*pAs2,*pAs3,*pA4;
    float *px0,*px1,*px2,*px3,*px4,*pxg,*pxu,*pxcat,*pU,*pZ;
    float *pscore,*pvals,*pwn;
    float *pdinv[5], *pfill[5];
    int *pperm0,*pperm1,*pperm2,*pperm3,*pcnt,*pbucket,*pdegi,*pselfc;
    cudaGetSymbolAddress((void**)&pAaug, g_Aaug);
    cudaGetSymbolAddress((void**)&pAs1,  g_As1);
    cudaGetSymbolAddress((void**)&pAs2,  g_As2);
    cudaGetSymbolAddress((void**)&pAs3,  g_As3);
    cudaGetSymbolAddress((void**)&pA4,   g_A4);
    cudaGetSymbolAddress((void**)&px0,   g_x0);
    cudaGetSymbolAddress((void**)&px1,   g_x1);
    cudaGetSymbolAddress((void**)&px2,   g_x2);
    cudaGetSymbolAddress((void**)&px3,   g_x3);
    cudaGetSymbolAddress((void**)&px4,   g_x4);
    cudaGetSymbolAddress((void**)&pxg,   g_xg);
    cudaGetSymbolAddress((void**)&pxu,   g_xu);
    cudaGetSymbolAddress((void**)&pxcat, g_xcat);
    cudaGetSymbolAddress((void**)&pU,    g_bU);
    cudaGetSymbolAddress((void**)&pZ,    g_bZ);
    cudaGetSymbolAddress((void**)&pdinv[0], g_dinv0); cudaGetSymbolAddress((void**)&pfill[0], g_fill0);
    cudaGetSymbolAddress((void**)&pdinv[1], g_dinv1); cudaGetSymbolAddress((void**)&pfill[1], g_fill1);
    cudaGetSymbolAddress((void**)&pdinv[2], g_dinv2); cudaGetSymbolAddress((void**)&pfill[2], g_fill2);
    cudaGetSymbolAddress((void**)&pdinv[3], g_dinv3); cudaGetSymbolAddress((void**)&pfill[3], g_fill3);
    cudaGetSymbolAddress((void**)&pdinv[4], g_dinv4); cudaGetSymbolAddress((void**)&pfill[4], g_fill4);
    cudaGetSymbolAddress((void**)&pscore,g_score);
    cudaGetSymbolAddress((void**)&pvals, g_vals);
    cudaGetSymbolAddress((void**)&pwn,   g_wn);
    cudaGetSymbolAddress((void**)&pperm0,g_perm0);
    cudaGetSymbolAddress((void**)&pperm1,g_perm1);
    cudaGetSymbolAddress((void**)&pperm2,g_perm2);
    cudaGetSymbolAddress((void**)&pperm3,g_perm3);
    cudaGetSymbolAddress((void**)&pcnt,  g_cnt);
    cudaGetSymbolAddress((void**)&pdegi, g_degi);
    cudaGetSymbolAddress((void**)&pselfc,g_selfc);
    cudaGetSymbolAddress((void**)&pbucket,g_bucket);

    auto gemm = [&](const float* A, const float* B, float* C, int M, int N, int K, int flags,
                    const float* dv, const float* fl, const float* bias, const float* Uin){
        if (N <= 32){
            dim3 g((N + 31)/32, M/128);
            k_gemm<32,2><<<g,256>>>(A,B,C,M,N,K,flags,dv,fl,bias,Uin);
        } else if (N <= 64){
            dim3 g((N + 63)/64, M/128);
            k_gemm<64,4><<<g,256>>>(A,B,C,M,N,K,flags,dv,fl,bias,Uin);
        } else {
            dim3 g((N + 127)/128, M/128);
            k_gemm<128,8><<<g,256>>>(A,B,C,M,N,K,flags,dv,fl,bias,Uin);
        }
    };
    // dense-level GCN: U = dinv*(xW); out = dinv*(A@U + fill*U) + b [relu]
    auto gcnD = [&](const float* A, int n, const float* dv, const float* fl,
                    const float* x, int fin, const float* W, const float* b,
                    int fout, float* out, bool relu){
        gemm(x, W, pU, n, fout, fin, 8, dv, nullptr, nullptr, nullptr);
        gemm(A, pU, out, n, fout, n, 16 | (relu ? 32 : 0), dv, fl, b, pU);
    };
    // sparse level-0 GCN via edge-parallel SpMM
    auto gcn0 = [&](const float* x, int fin, const float* W, const float* b,
                    int fout, float* out, bool relu){
        gemm(x, W, pU, 4096, fout, fin, 8, pdinv[0], nullptr, nullptr, nullptr);
        cudaMemsetAsync(pZ, 0, (size_t)4096*fout*sizeof(float), 0);
        k_spmm<<<(E*32 + 255)/256, 256>>>(eidx, E, pU, pZ, fout);
        int tot = 4096*fout;
        k_gcn_epi<<<(tot + 255)/256, 256>>>(pZ, pU, pdinv[0], pfill[0], b, out, 4096, fout, relu ? 1 : 0);
    };
    auto topk = [&](const float* x, int n, int F, const float* w, int k, int* perm){
        k_wnorm<<<1, 256>>>(w, F, pwn);
        k_score<<<(n + 255)/256, 256>>>(x, n, F, w, pwn, pscore);
        k_topk<<<(n + 255)/256, 256>>>(pscore, n, k, perm, pvals);
    };

    // ---- level-0 degrees from edge list ----
    cudaMemsetAsync(pdegi, 0, 4096*sizeof(int), 0);
    cudaMemsetAsync(pselfc, 0, 4096*sizeof(int), 0);
    k_edge_stats<<<(E + 255)/256, 256>>>(eidx, E, pdegi, pselfc);
    k_deg0_fin<<<(4096 + 255)/256, 256>>>(pdegi, pselfc, pdinv[0], pfill[0], 4096);

    // ---- build Aaug (augmented A0) directly, sparse ----
    cudaMemsetAsync(pAaug, 0, (size_t)4096*4096*sizeof(float), 0);
    k_scatter_aug<<<(E + 255)/256, 256>>>(eidx, E, pAaug, 4096);
    cudaMemsetAsync(pcnt, 0, 4096*sizeof(int), 0);
    k_bucket_fill<<<(E + 255)/256, 256>>>(eidx, E, pcnt, pbucket);
    k_aug0_join<<<(E + 255)/256, 256>>>(eidx, E, pcnt, pbucket, pAaug, 4096);

    // ---- down level 0 (sparse) ----
    gcn0(x_in, 128, Wd[0], bd[0], 32, px0, true);

    // ---- pool to 2048 ----
    topk(px0, 4096, 32, pv[0], 2048, pperm0);
    k_gather_x<<<(2048*32 + 255)/256, 256>>>(px0, 32, pperm0, pvals, pxg, 2048);
    k_gather_A<<<(unsigned)(((size_t)2048*2048 + 255)/256), 256>>>(pAaug, 4096, pperm0, pAs1, 2048);
    k_deg<<<(2048 + 7)/8, 256>>>(pAs1, 2048, pdinv[1], pfill[1]);
    gcnD(pAs1, 2048, pdinv[1], pfill[1], pxg, 32, Wd[1], bd[1], 64, px1, true);

    // ---- level 2: dense augment at 2048, pool to 1024 ----
    gemm(pAs1, pAs1, pAaug, 2048, 2048, 2048, 1|2|4, nullptr,nullptr,nullptr,nullptr);
    topk(px1, 2048, 64, pv[1], 1024, pperm1);
    k_gather_x<<<(1024*64 + 255)/256, 256>>>(px1, 64, pperm1, pvals, pxg, 1024);
    k_gather_A<<<(unsigned)(((size_t)1024*1024 + 255)/256), 256>>>(pAaug, 2048, pperm1, pAs2, 1024);
    k_deg<<<(1024 + 7)/8, 256>>>(pAs2, 1024, pdinv[2], pfill[2]);
    gcnD(pAs2, 1024, pdinv[2], pfill[2], pxg, 64, Wd[2], bd[2], 128, px2, true);

    // ---- level 3: dense augment at 1024, pool to 512 ----
    gemm(pAs2, pAs2, pAaug, 1024, 1024, 1024, 1|2|4, nullptr,nullptr,nullptr,nullptr);
    topk(px2, 1024, 128, pv[2], 512, pperm2);
    k_gather_x<<<(512*128 + 255)/256, 256>>>(px2, 128, pperm2, pvals, pxg, 512);
    k_gather_A<<<(unsigned)(((size_t)512*512 + 255)/256), 256>>>(pAaug, 1024, pperm2, pAs3, 512);
    k_deg<<<(512 + 7)/8, 256>>>(pAs3, 512, pdinv[3], pfill[3]);
    gcnD(pAs3, 512, pdinv[3], pfill[3], pxg, 128, Wd[3], bd[3], 256, px3, true);

    // ---- level 4: dense augment at 512, pool to 256 ----
    gemm(pAs3, pAs3, pAaug, 512, 512, 512, 1|2|4, nullptr,nullptr,nullptr,nullptr);
    topk(px3, 512, 256, pv[3], 256, pperm3);
    k_gather_x<<<(256*256 + 255)/256, 256>>>(px3, 256, pperm3, pvals, pxg, 256);
    k_gather_A<<<(unsigned)(((size_t)256*256 + 255)/256), 256>>>(pAaug, 512, pperm3, pA4, 256);
    k_deg<<<(256 + 7)/8, 256>>>(pA4, 256, pdinv[4], pfill[4]);
    gcnD(pA4, 256, pdinv[4], pfill[4], pxg, 256, Wd[4], bd[4], 512, px4, true);

    // ---- up path ----
    // up0: res=x3 (512x256), perm3, x4 (256x512), C=256 -> xcat 512x512
    k_concat_res<<<(512*512 + 255)/256, 256>>>(px3, 256, pxcat, 512);
    k_scatter_up<<<(256*256 + 255)/256, 256>>>(px4, 512, 256, pperm3, pxcat, 256);
    gcnD(pAs3, 512, pdinv[3], pfill[3], pxcat, 512, Wu[0], bu[0], 256, pxu, true);

    // up1: res=x2 (1024x128), perm2, xu (512x256), C=128 -> xcat 1024x256
    k_concat_res<<<(1024*256 + 255)/256, 256>>>(px2, 128, pxcat, 1024);
    k_scatter_up<<<(512*128 + 255)/256, 256>>>(pxu, 256, 128, pperm2, pxcat, 512);
    gcnD(pAs2, 1024, pdinv[2], pfill[2], pxcat, 256, Wu[1], bu[1], 128, pxu, true);

    // up2: res=x1 (2048x64), perm1, xu (1024x128), C=64 -> xcat 2048x128
    k_concat_res<<<(2048*128 + 255)/256, 256>>>(px1, 64, pxcat, 2048);
    k_scatter_up<<<(1024*64 + 255)/256, 256>>>(pxu, 128, 64, pperm1, pxcat, 1024);
    gcnD(pAs1, 2048, pdinv[1], pfill[1], pxcat, 128, Wu[2], bu[2], 64, pxu, true);

    // up3: res=x0 (4096x32), perm0, xu (2048x64), C=32 -> xcat 4096x64, NO relu (sparse level)
    k_concat_res<<<(4096*64 + 255)/256, 256>>>(px0, 32, pxcat, 4096);
    k_scatter_up<<<(2048*32 + 255)/256, 256>>>(pxu, 64, 32, pperm0, pxcat, 2048);
    gcn0(pxcat, 64, Wu[3], bu[3], 32, pxu, false);

    // ---- final GCN (sparse) + softmax ----
    gcn0(pxu, 32, Wo, bo, 37, pxcat, false);
    k_softmax<<<(4096 + 255)/256, 256>>>(pxcat, (float*)d_out, 4096, 37);
}

// round 7
// speedup vs baseline: 6.0773x; 3.0504x over previous
#include <cuda_runtime.h>
#include <math.h>

#define CAP 192

// ---------------- static device scratch (no allocation allowed) ----------------
__device__ float g_S[(size_t)4096*4096];      // scratch: Gr | Gc | split-K partials
__device__ float g_As1[(size_t)2048*2048];
__device__ float g_As2[(size_t)1024*1024];
__device__ float g_As3[(size_t)512*512];
__device__ float g_A4[(size_t)256*256];
__device__ float g_x0[4096*32];
__device__ float g_x1[2048*64];
__device__ float g_x2[1024*128];
__device__ float g_x3[512*256];
__device__ float g_x4[256*512];
__device__ float g_xg[2048*64];
__device__ float g_xu[4096*64];
__device__ float g_xcat[4096*64];
__device__ float g_bU[4096*64];
__device__ float g_bZ[4096*64];
__device__ float g_dinv0[4096], g_fill0[4096];
__device__ float g_dinv1[2048], g_fill1[2048];
__device__ float g_dinv2[1024], g_fill2[1024];
__device__ float g_dinv3[512],  g_fill3[512];
__device__ float g_dinv4[256],  g_fill4[256];
__device__ float g_score[4096];
__device__ float g_vals[4096];
__device__ float g_wn[1];
__device__ int   g_perm0[2048];
__device__ int   g_perm1[1024];
__device__ int   g_perm2[512];
__device__ int   g_perm3[256];
__device__ int   g_cnt[4096];
__device__ int   g_degi[4096];
__device__ int   g_selfc[4096];
__device__ int   g_inv[4096];
__device__ int   g_bucket[4096*CAP];

// ---------------- sparse level-0 kernels ----------------

__global__ void k_edge_stats(const int* __restrict__ e, int E, int* degi, int* selfc){
    int i = blockIdx.x*blockDim.x + threadIdx.x;
    if (i >= E) return;
    int s = e[i], d = e[E+i];
    atomicAdd(&degi[d], 1);
    if (s == d) atomicAdd(&selfc[d], 1);
}

__global__ void k_deg0_fin(const int* __restrict__ degi, const int* __restrict__ selfc,
                           float* dinv, float* fill, int n){
    int i = blockIdx.x*blockDim.x + threadIdx.x;
    if (i >= n) return;
    float f = (selfc[i] == 0) ? 2.0f : 0.0f;
    float deg = (float)degi[i] + f;
    dinv[i] = (deg > 0.f) ? 1.0f/sqrtf(deg) : 0.0f;
    fill[i] = f;
}

__global__ void k_bucket_fill(const int* __restrict__ e, int E, int* cnt, int* bucket){
    int i = blockIdx.x*blockDim.x + threadIdx.x;
    if (i >= E) return;
    int s = e[i], d = e[E+i];
    if (s == d) return;
    int p = atomicAdd(&cnt[s], 1);
    if (p < CAP) bucket[s*CAP + p] = d;
}

__global__ void k_set_inv(const int* __restrict__ perm, int* inv, int k){
    int r = blockIdx.x*blockDim.x + threadIdx.x;
    if (r < k) inv[perm[r]] = r;
}

// As1 += 2 on offdiag edges mapped through inverse perm (the 2*Aoff term)
__global__ void k_scatter_aug_inv(const int* __restrict__ e, int E, const int* __restrict__ inv,
                                  float* A, int k){
    int i = blockIdx.x*blockDim.x + threadIdx.x;
    if (i >= E) return;
    int s = e[i], d = e[E+i];
    if (s == d) return;
    int ir = inv[d], ic = inv[s];
    if (ir >= 0 && ic >= 0) atomicAdd(&A[(size_t)ir*k + ic], 2.0f);
}

// As1 += offdiag(Aoff^2) via edge self-join, mapped through inverse perm
__global__ void k_join_inv(const int* __restrict__ e, int E, const int* __restrict__ cnt,
                           const int* __restrict__ bucket, const int* __restrict__ inv,
                           float* A, int k){
    int i = blockIdx.x*blockDim.x + threadIdx.x;
    if (i >= E) return;
    int s2 = e[i], d2 = e[E+i];
    if (s2 == d2) return;
    int ic = inv[s2];
    if (ic < 0) return;
    int c = min(cnt[d2], CAP);
    const int* b = bucket + d2*CAP;
    for (int t = 0; t < c; t++){
        int d1 = b[t];
        if (d1 == s2) continue;
        int ir = inv[d1];
        if (ir >= 0) atomicAdd(&A[(size_t)ir*k + ic], 1.0f);
    }
}

// Z[d][:] += U[s][:] per edge; warp-per-edge
__global__ void k_spmm(const int* __restrict__ e, int E, const float* __restrict__ U,
                       float* Z, int F){
    int w = (blockIdx.x*blockDim.x + threadIdx.x) >> 5;
    int lane = threadIdx.x & 31;
    if (w >= E) return;
    int s = e[w], d = e[E+w];
    const float* ur = U + (size_t)s*F;
    float* zr = Z + (size_t)d*F;
    for (int f = lane; f < F; f += 32) atomicAdd(&zr[f], ur[f]);
}

// ---------------- dense helpers ----------------

// deg = rowsum(A) + fill (fill=2 where diag==0); dinv = 1/sqrt(deg)
__global__ void k_deg(const float* __restrict__ A, int n, float* dinv, float* fill){
    int row  = blockIdx.x*(blockDim.x >> 5) + (threadIdx.x >> 5);
    int lane = threadIdx.x & 31;
    if (row >= n) return;
    const float* r = A + (size_t)row*n;
    float s = 0.f;
    for (int j = lane; j < n; j += 32) s += r[j];
    #pragma unroll
    for (int o = 16; o; o >>= 1) s += __shfl_xor_sync(0xffffffffu, s, o);
    if (lane == 0){
        float f = (r[row] == 0.0f) ? 2.0f : 0.0f;
        float deg = s + f;
        dinv[row] = (deg > 0.f) ? 1.0f/sqrtf(deg) : 0.0f;
        fill[row] = f;
    }
}

// Vectorized GEMM, no guards: M%BM==0, N%BN==0, kc%16==0, N%4==0.
// Writes raw tile into part + blockIdx.z*M*N over K-range [z*kc,(z+1)*kc).
template<int BM,int BN,int TM,int TN>
__global__ __launch_bounds__(256) void k_gemm_f4(
    const float* __restrict__ A, const float* __restrict__ B, float* __restrict__ part,
    int M, int N, int K, int kc)
{
    const int BK = 16;
    __shared__ float As[BK][BM+4];
    __shared__ float Bs[BK][BN];
    int tid = threadIdx.x;
    int tx = tid & 15, ty = tid >> 4;
    int bm = blockIdx.y*BM, bn = blockIdx.x*BN;
    int k0 = blockIdx.z*kc;
    float acc[TM][TN] = {};
    for (int kb = k0; kb < k0 + kc; kb += BK){
        #pragma unroll
        for (int q = 0; q < (BM*BK)/1024; q++){
            int idx = tid + q*256;
            int row = idx >> 2, c4 = (idx & 3) << 2;
            float4 v = *reinterpret_cast<const float4*>(&A[(size_t)(bm+row)*K + kb + c4]);
            As[c4+0][row] = v.x; As[c4+1][row] = v.y;
            As[c4+2][row] = v.z; As[c4+3][row] = v.w;
        }
        #pragma unroll
        for (int q = 0; q < (BK*BN)/1024; q++){
            int idx = tid + q*256;
            int row = idx/(BN/4), c4 = (idx % (BN/4)) << 2;
            *reinterpret_cast<float4*>(&Bs[row][c4]) =
                *reinterpret_cast<const float4*>(&B[(size_t)(kb+row)*N + bn + c4]);
        }
        __syncthreads();
        #pragma unroll
        for (int k = 0; k < BK; k++){
            float a[TM], b[TN];
            #pragma unroll
            for (int i = 0; i < TM; i += 4)
                *reinterpret_cast<float4*>(&a[i]) = *reinterpret_cast<const float4*>(&As[k][ty*TM + i]);
            #pragma unroll
            for (int j = 0; j < TN; j += 4)
                *reinterpret_cast<float4*>(&b[j]) = *reinterpret_cast<const float4*>(&Bs[k][tx*TN + j]);
            #pragma unroll
            for (int i = 0; i < TM; i++)
                #pragma unroll
                for (int j = 0; j < TN; j++)
                    acc[i][j] += a[i]*b[j];
        }
        __syncthreads();
    }
    float* out = part + (size_t)blockIdx.z*M*N;
    #pragma unroll
    for (int i = 0; i < TM; i++){
        int gm = bm + ty*TM + i;
        #pragma unroll
        for (int j = 0; j < TN; j += 4){
            int gn = bn + tx*TN + j;
            *reinterpret_cast<float4*>(&out[(size_t)gm*N + gn]) =
                *reinterpret_cast<const float4*>(&acc[i][j]);
        }
    }
}

// N-guarded GEMM for skinny N (<=64): BM=128, BK=8, TM=8; partial output + split-K.
// Requires M%128==0, kc%8==0, K%4==0.
template<int BN,int TN>
__global__ __launch_bounds__(256) void k_gemm_sm(
    const float* __restrict__ A, const float* __restrict__ B, float* __restrict__ part,
    int M, int N, int K, int kc)
{
    const int BM = 128, BK = 8, TM = 8;
    __shared__ float As[BK][BM+4];
    __shared__ float Bs[BK][BN];
    int tid = threadIdx.x;
    int tx = tid % (BN/TN), ty = tid / (BN/TN);
    int bm = blockIdx.y*BM, bn = blockIdx.x*BN;
    int k0 = blockIdx.z*kc;
    float acc[TM][TN] = {};
    int arow = tid >> 1, acol = (tid & 1)*4;
    for (int kb = k0; kb < k0 + kc; kb += BK){
        float4 av = *reinterpret_cast<const float4*>(&A[(size_t)(bm+arow)*K + kb + acol]);
        As[acol+0][arow] = av.x; As[acol+1][arow] = av.y;
        As[acol+2][arow] = av.z; As[acol+3][arow] = av.w;
        #pragma unroll
        for (int t = 0; t < (BK*BN)/256; t++){
            int el = tid + t*256;
            int kr = el / BN, cc = el % BN;
            int gn = bn + cc;
            Bs[kr][cc] = (gn < N) ? B[(size_t)(kb+kr)*N + gn] : 0.f;
        }
        __syncthreads();
        #pragma unroll
        for (int k = 0; k < BK; k++){
            float a[TM], b[TN];
            #pragma unroll
            for (int i = 0; i < TM; i++) a[i] = As[k][ty*TM + i];
            #pragma unroll
            for (int j = 0; j < TN; j++) b[j] = Bs[k][tx*TN + j];
            #pragma unroll
            for (int i = 0; i < TM; i++)
                #pragma unroll
                for (int j = 0; j < TN; j++)
                    acc[i][j] += a[i]*b[j];
        }
        __syncthreads();
    }
    float* out = part + (size_t)blockIdx.z*M*N;
    #pragma unroll
    for (int i = 0; i < TM; i++){
        int gm = bm + ty*TM + i;
        #pragma unroll
        for (int j = 0; j < TN; j++){
            int gn = bn + tx*TN + j;
            if (gn < N) out[(size_t)gm*N + gn] = acc[i][j];
        }
    }
}

// Reduce SK partials (fixed order -> deterministic) + epilogue.
// flags: 4 zero diag, 8 scale dinv[m], 16 gcn epi, 32 relu
__global__ void k_redepi(float* out, const float* __restrict__ part, int SK, int M, int N,
                         int flags, const float* __restrict__ dinv, const float* __restrict__ fl,
                         const float* __restrict__ bias, const float* __restrict__ Uin)
{
    size_t idx = (size_t)blockIdx.x*blockDim.x + threadIdx.x;
    if (idx >= (size_t)M*N) return;
    int m = (int)(idx / N), n = (int)(idx % N);
    size_t MN = (size_t)M*N;
    float v = 0.f;
    for (int z = 0; z < SK; z++) v += part[z*MN + idx];
    if (flags & 16)      v = dinv[m]*(v + fl[m]*Uin[idx]) + bias[n];
    else if (flags & 8)  v *= dinv[m];
    if (flags & 32) v = fmaxf(v, 0.f);
    if ((flags & 4) && m == n) v = 0.f;
    out[idx] = v;
}

// ---------------- augment operand gathers (B = A + I) ----------------

__global__ void k_gather_rows(const float* __restrict__ A, int n, const int* __restrict__ perm,
                              float* Gr, int k){
    size_t t = (size_t)blockIdx.x*blockDim.x + threadIdx.x;
    size_t tot = (size_t)k*(n/4);
    if (t >= tot) return;
    int r = (int)(t / (n/4));
    int c4 = (int)(t % (n/4))*4;
    *reinterpret_cast<float4*>(&Gr[(size_t)r*n + c4]) =
        *reinterpret_cast<const float4*>(&A[(size_t)perm[r]*n + c4]);
}
__global__ void k_diag_r(float* Gr, int n, const int* __restrict__ perm, int k){
    int r = blockIdx.x*blockDim.x + threadIdx.x;
    if (r < k) Gr[(size_t)r*n + perm[r]] += 1.f;
}
__global__ void k_gather_cols(const float* __restrict__ A, int n, const int* __restrict__ perm,
                              float* Gc, int k){
    size_t t = (size_t)blockIdx.x*blockDim.x + threadIdx.x;
    if (t >= (size_t)n*k) return;
    int j = (int)(t / k), c = (int)(t % k);
    Gc[t] = A[(size_t)j*n + perm[c]];
}
__global__ void k_diag_c(float* Gc, const int* __restrict__ perm, int k){
    int c = blockIdx.x*blockDim.x + threadIdx.x;
    if (c < k) Gc[(size_t)perm[c]*k + c] += 1.f;
}

// ---------------- gcn epilogue (sparse path) ----------------

__global__ void k_gcn_epi(const float* Z, const float* U, const float* dinv, const float* fill,
                          const float* __restrict__ b, float* out, int n, int F, int relu){
    int idx = blockIdx.x*blockDim.x + threadIdx.x;
    if (idx >= n*F) return;
    int i = idx / F, f = idx % F;
    float v = dinv[i]*(Z[idx] + fill[i]*U[idx]) + b[f];
    if (relu) v = fmaxf(v, 0.f);
    out[idx] = v;
}

// ---------------- topk / gather / misc ----------------

__global__ void k_wnorm(const float* w, int F, float* out){
    __shared__ float sh[256];
    float s = 0.f;
    for (int i = threadIdx.x; i < F; i += 256) s += w[i]*w[i];
    sh[threadIdx.x] = s; __syncthreads();
    for (int o = 128; o; o >>= 1){
        if (threadIdx.x < o) sh[threadIdx.x] += sh[threadIdx.x + o];
        __syncthreads();
    }
    if (threadIdx.x == 0) out[0] = sqrtf(sh[0]);
}

__global__ void k_score(const float* x, int n, int F, const float* __restrict__ w,
                        const float* nrm, float* score){
    int i = blockIdx.x*blockDim.x + threadIdx.x;
    if (i >= n) return;
    const float* r = x + (size_t)i*F;
    float s = 0.f;
    for (int f = 0; f < F; f++) s += r[f]*w[f];
    score[i] = tanhf(s / nrm[0]);
}

// stable top-k by exact ranking: matches jax.lax.top_k ordering
__global__ void k_topk(const float* __restrict__ s, int n, int k, int* idx, float* vals){
    int i = blockIdx.x*blockDim.x + threadIdx.x;
    if (i >= n) return;
    float si = s[i];
    int c = 0;
    for (int j = 0; j < n; j++){
        float sj = s[j];
        c += (sj > si) || (sj == si && j < i);
    }
    if (c < k){ idx[c] = i; vals[c] = si; }
}

__global__ void k_gather_x(const float* x, int F, const int* idx, const float* vals,
                           float* out, int k){
    int t = blockIdx.x*blockDim.x + threadIdx.x;
    if (t >= k*F) return;
    int r = t / F, f = t % F;
    out[t] = x[(size_t)idx[r]*F + f] * vals[r];
}

__global__ void k_concat_res(const float* res, int C, float* xcat, int n){
    int t = blockIdx.x*blockDim.x + threadIdx.x;
    int W = 2*C;
    if (t >= n*W) return;
    int r = t / W, f = t % W;
    xcat[t] = (f < C) ? res[(size_t)r*C + f] : 0.f;
}

__global__ void k_scatter_up(const float* x, int Fx, int C, const int* perm,
                             float* xcat, int nsmall){
    int t = blockIdx.x*blockDim.x + threadIdx.x;
    if (t >= nsmall*C) return;
    int r = t / C, f = t % C;
    xcat[(size_t)perm[r]*(2*C) + C + f] = x[(size_t)r*Fx + f];
}

__global__ void k_softmax(const float* z, float* out, int n, int C){
    int i = blockIdx.x*blockDim.x + threadIdx.x;
    if (i >= n) return;
    const float* r = z + (size_t)i*C;
    float m = -1e30f;
    for (int c = 0; c < C; c++) m = fmaxf(m, r[c]);
    float s = 0.f;
    for (int c = 0; c < C; c++) s += expf(r[c] - m);
    float inv = 1.0f/s;
    for (int c = 0; c < C; c++) out[(size_t)i*C + c] = expf(r[c] - m)*inv;
}

// ---------------- host orchestration ----------------

extern "C" void kernel_launch(void* const* d_in, const int* in_sizes, int n_in,
                              void* d_out, int out_size){
    const float* x_in = (const float*)d_in[0];
    const int*   eidx = (const int*)d_in[1];
    const float *Wd[5], *bd[5], *pv[4], *Wu[4], *bu[4];
    for (int i = 0; i < 5; i++){ Wd[i] = (const float*)d_in[2 + 2*i]; bd[i] = (const float*)d_in[3 + 2*i]; }
    for (int i = 0; i < 4; i++)  pv[i] = (const float*)d_in[12 + i];
    for (int i = 0; i < 4; i++){ Wu[i] = (const float*)d_in[16 + 2*i]; bu[i] = (const float*)d_in[17 + 2*i]; }
    const float* Wo = (const float*)d_in[24];
    const float* bo = (const float*)d_in[25];
    int E = in_sizes[1] / 2;

    float *pS,*pAs1,*pAs2,*pAs3,*pA4;
    float *px0,*px1,*px2,*px3,*px4,*pxg,*pxu,*pxcat,*pU,*pZ;
    float *pscore,*pvals,*pwn;
    float *pdinv[5], *pfill[5];
    int *pperm[4],*pcnt,*pbucket,*pdegi,*pselfc,*pinv;
    cudaGetSymbolAddress((void**)&pS,    g_S);
    cudaGetSymbolAddress((void**)&pAs1,  g_As1);
    cudaGetSymbolAddress((void**)&pAs2,  g_As2);
    cudaGetSymbolAddress((void**)&pAs3,  g_As3);
    cudaGetSymbolAddress((void**)&pA4,   g_A4);
    cudaGetSymbolAddress((void**)&px0,   g_x0);
    cudaGetSymbolAddress((void**)&px1,   g_x1);
    cudaGetSymbolAddress((void**)&px2,   g_x2);
    cudaGetSymbolAddress((void**)&px3,   g_x3);
    cudaGetSymbolAddress((void**)&px4,   g_x4);
    cudaGetSymbolAddress((void**)&pxg,   g_xg);
    cudaGetSymbolAddress((void**)&pxu,   g_xu);
    cudaGetSymbolAddress((void**)&pxcat, g_xcat);
    cudaGetSymbolAddress((void**)&pU,    g_bU);
    cudaGetSymbolAddress((void**)&pZ,    g_bZ);
    cudaGetSymbolAddress((void**)&pdinv[0], g_dinv0); cudaGetSymbolAddress((void**)&pfill[0], g_fill0);
    cudaGetSymbolAddress((void**)&pdinv[1], g_dinv1); cudaGetSymbolAddress((void**)&pfill[1], g_fill1);
    cudaGetSymbolAddress((void**)&pdinv[2], g_dinv2); cudaGetSymbolAddress((void**)&pfill[2], g_fill2);
    cudaGetSymbolAddress((void**)&pdinv[3], g_dinv3); cudaGetSymbolAddress((void**)&pfill[3], g_fill3);
    cudaGetSymbolAddress((void**)&pdinv[4], g_dinv4); cudaGetSymbolAddress((void**)&pfill[4], g_fill4);
    cudaGetSymbolAddress((void**)&pscore, g_score);
    cudaGetSymbolAddress((void**)&pvals,  g_vals);
    cudaGetSymbolAddress((void**)&pwn,    g_wn);
    cudaGetSymbolAddress((void**)&pperm[0], g_perm0);
    cudaGetSymbolAddress((void**)&pperm[1], g_perm1);
    cudaGetSymbolAddress((void**)&pperm[2], g_perm2);
    cudaGetSymbolAddress((void**)&pperm[3], g_perm3);
    cudaGetSymbolAddress((void**)&pcnt,   g_cnt);
    cudaGetSymbolAddress((void**)&pdegi,  g_degi);
    cudaGetSymbolAddress((void**)&pselfc, g_selfc);
    cudaGetSymbolAddress((void**)&pinv,   g_inv);
    cudaGetSymbolAddress((void**)&pbucket,g_bucket);

    float* pGr   = pS;             // up to 2M floats
    float* pGc   = pS + 4194304;   // up to 2M floats
    float* ppart = pS + 8388608;   // up to 4M floats (SK partials)

    // GEMM launchers (all write raw partials into ppart)
    auto g128 = [&](const float* A, const float* B, int M, int N, int K, int SK){
        dim3 g(N/128, M/128, SK);
        k_gemm_f4<128,128,8,8><<<g,256>>>(A,B,ppart,M,N,K,K/SK);
    };
    auto g64 = [&](const float* A, const float* B, int M, int N, int K, int SK){
        dim3 g(N/64, M/64, SK);
        k_gemm_f4<64,64,4,4><<<g,256>>>(A,B,ppart,M,N,K,K/SK);
    };
    auto gsm = [&](const float* A, const float* B, int M, int N, int K, int SK){
        if (N <= 32){
            dim3 g(1, M/128, SK);
            k_gemm_sm<32,2><<<g,256>>>(A,B,ppart,M,N,K,K/SK);
        } else {
            dim3 g(1, M/128, SK);
            k_gemm_sm<64,4><<<g,256>>>(A,B,ppart,M,N,K,K/SK);
        }
    };
    auto red = [&](float* out, int SK, int M, int N, int flags,
                   const float* dv, const float* fl, const float* bias, const float* Uin){
        size_t tot = (size_t)M*N;
        k_redepi<<<(unsigned)((tot + 255)/256), 256>>>(out, ppart, SK, M, N, flags, dv, fl, bias, Uin);
    };
    auto topk = [&](const float* x, int n, int F, const float* w, int k, int* perm){
        k_wnorm<<<1, 256>>>(w, F, pwn);
        k_score<<<(n + 255)/256, 256>>>(x, n, F, w, pwn, pscore);
        k_topk<<<(n + 255)/256, 256>>>(pscore, n, k, perm, pvals);
    };
    // dense GCN: U = dinv*(xW); out = dinv*(A@U + fill*U) + b [relu]
    auto gcnD = [&](const float* A, int n, const float* dv, const float* fl,
                    const float* x, int fin, const float* W, const float* b,
                    int fout, float* out, bool relu){
        int skx = (fin >= 256) ? 2 : 1;
        if (fout <= 64) gsm(x, W, n, fout, fin, skx);
        else            g64(x, W, n, fout, fin, skx);
        red(pU, skx, n, fout, 8, dv, nullptr, nullptr, nullptr);
        int ska = (n >= 512) ? 4 : 2;
        if (fout <= 64){ ska = 8; gsm(A, pU, n, fout, n, ska); }
        else             g64(A, pU, n, fout, n, ska);
        red(out, ska, n, fout, 16 | (relu ? 32 : 0), dv, fl, b, pU);
    };
    // sparse level-0 GCN
    auto gcn0 = [&](const float* x, int fin, const float* W, const float* b,
                    int fout, float* out, bool relu){
        gsm(x, W, 4096, fout, fin, 1);
        red(pU, 1, 4096, fout, 8, pdinv[0], nullptr, nullptr, nullptr);
        cudaMemsetAsync(pZ, 0, (size_t)4096*fout*sizeof(float), 0);
        k_spmm<<<(E*32 + 255)/256, 256>>>(eidx, E, pU, pZ, fout);
        int tot = 4096*fout;
        k_gcn_epi<<<(tot + 255)/256, 256>>>(pZ, pU, pdinv[0], pfill[0], b, out, 4096, fout, relu ? 1 : 0);
    };
    // pooled augment: Adst(k x k) = (Asrc+I)[perm,:] @ (Asrc+I)[:,perm], zero diag
    auto aug = [&](const float* Asrc, int n, const int* perm, int k, float* Adst, bool big){
        size_t rt = (size_t)k*(n/4);
        k_gather_rows<<<(unsigned)((rt + 255)/256), 256>>>(Asrc, n, perm, pGr, k);
        k_diag_r<<<(k + 255)/256, 256>>>(pGr, n, perm, k);
        size_t ct = (size_t)n*k;
        k_gather_cols<<<(unsigned)((ct + 255)/256), 256>>>(Asrc, n, perm, pGc, k);
        k_diag_c<<<(k + 255)/256, 256>>>(pGc, perm, k);
        int SK = 4;
        if (big) g128(pGr, pGc, k, k, n, SK);
        else     g64 (pGr, pGc, k, k, n, SK);
        red(Adst, SK, k, k, 4, nullptr, nullptr, nullptr, nullptr);
    };

    // ---- level-0 degrees + buckets from edge list ----
    cudaMemsetAsync(pdegi, 0, 4096*sizeof(int), 0);
    cudaMemsetAsync(pselfc, 0, 4096*sizeof(int), 0);
    k_edge_stats<<<(E + 255)/256, 256>>>(eidx, E, pdegi, pselfc);
    k_deg0_fin<<<(4096 + 255)/256, 256>>>(pdegi, pselfc, pdinv[0], pfill[0], 4096);
    cudaMemsetAsync(pcnt, 0, 4096*sizeof(int), 0);
    k_bucket_fill<<<(E + 255)/256, 256>>>(eidx, E, pcnt, pbucket);

    // ---- down level 0 (sparse) ----
    gcn0(x_in, 128, Wd[0], bd[0], 32, px0, true);

    // ---- pool to 2048; build As1 directly via inverse perm (sparse join) ----
    topk(px0, 4096, 32, pv[0], 2048, pperm[0]);
    k_gather_x<<<(2048*32 + 255)/256, 256>>>(px0, 32, pperm[0], pvals, pxg, 2048);
    cudaMemsetAsync(pAs1, 0, (size_t)2048*2048*sizeof(float), 0);
    cudaMemsetAsync(pinv, 0xFF, 4096*sizeof(int), 0);
    k_set_inv<<<(2048 + 255)/256, 256>>>(pperm[0], pinv, 2048);
    k_scatter_aug_inv<<<(E + 255)/256, 256>>>(eidx, E, pinv, pAs1, 2048);
    k_join_inv<<<(E + 255)/256, 256>>>(eidx, E, pcnt, pbucket, pinv, pAs1, 2048);
    k_deg<<<(2048 + 7)/8, 256>>>(pAs1, 2048, pdinv[1], pfill[1]);
    gcnD(pAs1, 2048, pdinv[1], pfill[1], pxg, 32, Wd[1], bd[1], 64, px1, true);

    // ---- level 2: pooled augment (1024x1024x2048), GCN ----
    topk(px1, 2048, 64, pv[1], 1024, pperm[1]);
    aug(pAs1, 2048, pperm[1], 1024, pAs2, true);
    k_gather_x<<<(1024*64 + 255)/256, 256>>>(px1, 64, pperm[1], pvals, pxg, 1024);
    k_deg<<<(1024 + 7)/8, 256>>>(pAs2, 1024, pdinv[2], pfill[2]);
    gcnD(pAs2, 1024, pdinv[2], pfill[2], pxg, 64, Wd[2], bd[2], 128, px2, true);

    // ---- level 3: pooled augment (512x512x1024), GCN ----
    topk(px2, 1024, 128, pv[2], 512, pperm[2]);
    aug(pAs2, 1024, pperm[2], 512, pAs3, false);
    k_gather_x<<<(512*128 + 255)/256, 256>>>(px2, 128, pperm[2], pvals, pxg, 512);
    k_deg<<<(512 + 7)/8, 256>>>(pAs3, 512, pdinv[3], pfill[3]);
    gcnD(pAs3, 512, pdinv[3], pfill[3], pxg, 128, Wd[3], bd[3], 256, px3, true);

    // ---- level 4: pooled augment (256x256x512), GCN ----
    topk(px3, 512, 256, pv[3], 256, pperm[3]);
    aug(pAs3, 512, pperm[3], 256, pA4, false);
    k_gather_x<<<(256*256 + 255)/256, 256>>>(px3, 256, pperm[3], pvals, pxg, 256);
    k_deg<<<(256 + 7)/8, 256>>>(pA4, 256, pdinv[4], pfill[4]);
    gcnD(pA4, 256, pdinv[4], pfill[4], pxg, 256, Wd[4], bd[4], 512, px4, true);

    // ---- up path ----
    k_concat_res<<<(512*512 + 255)/256, 256>>>(px3, 256, pxcat, 512);
    k_scatter_up<<<(256*256 + 255)/256, 256>>>(px4, 512, 256, pperm[3], pxcat, 256);
    gcnD(pAs3, 512, pdinv[3], pfill[3], pxcat, 512, Wu[0], bu[0], 256, pxu, true);

    k_concat_res<<<(1024*256 + 255)/256, 256>>>(px2, 128, pxcat, 1024);
    k_scatter_up<<<(512*128 + 255)/256, 256>>>(pxu, 256, 128, pperm[2], pxcat, 512);
    gcnD(pAs2, 1024, pdinv[2], pfill[2], pxcat, 256, Wu[1], bu[1], 128, pxu, true);

    k_concat_res<<<(2048*128 + 255)/256, 256>>>(px1, 64, pxcat, 2048);
    k_scatter_up<<<(1024*64 + 255)/256, 256>>>(pxu, 128, 64, pperm[1], pxcat, 1024);
    gcnD(pAs1, 2048, pdinv[1], pfill[1], pxcat, 128, Wu[2], bu[2], 64, pxu, true);

    k_concat_res<<<(4096*64 + 255)/256, 256>>>(px0, 32, pxcat, 4096);
    k_scatter_up<<<(2048*32 + 255)/256, 256>>>(pxu, 64, 32, pperm[0], pxcat, 2048);
    gcn0(pxcat, 64, Wu[3], bu[3], 32, pxu, false);

    // ---- final GCN (sparse) + softmax ----
    gcn0(pxu, 32, Wo, bo, 37, pxcat, false);
    k_softmax<<<(4096 + 255)/256, 256>>>(pxcat, (float*)d_out, 4096, 37);
}

// round 10
// speedup vs baseline: 7.3316x; 1.2064x over previous
#include <cuda_runtime.h>
#include <math.h>

#define CAP 192

// ---------------- static device scratch (no allocation allowed) ----------------
__device__ float g_S[(size_t)4096*4096];      // scratch: Gr | Gc | split-K partials
__device__ float g_As1[(size_t)2048*2048];
__device__ float g_As2[(size_t)1024*1024];
__device__ float g_As3[(size_t)512*512];
__device__ float g_A4[(size_t)256*256];
__device__ float g_x0[4096*32];
__device__ float g_x1[2048*64];
__device__ float g_x2[1024*128];
__device__ float g_x3[512*256];
__device__ float g_x4[256*512];
__device__ float g_xg[2048*64];
__device__ float g_xu[4096*64];
__device__ float g_xcat[4096*64];
__device__ float g_bU[4096*64];
__device__ float g_bZ[4096*64];
__device__ float g_dinv0[4096], g_fill0[4096];
__device__ float g_dinv1[2048], g_fill1[2048];
__device__ float g_dinv2[1024], g_fill2[1024];
__device__ float g_dinv3[512],  g_fill3[512];
__device__ float g_dinv4[256],  g_fill4[256];
__device__ float g_score[4096];
__device__ float g_vals[4096];
__device__ float g_wn[1];
__device__ int   g_perm0[2048];
__device__ int   g_perm1[1024];
__device__ int   g_perm2[512];
__device__ int   g_perm3[256];
__device__ int   g_cnt[4096];
__device__ int   g_tcnt[4096];
__device__ int   g_degi[4096];
__device__ int   g_selfc[4096];
__device__ int   g_inv[4096];
__device__ int   g_bucket[4096*CAP];

// ---------------- sparse level-0 kernels ----------------

__global__ void k_edge_stats(const int* __restrict__ e, int E, int* degi, int* selfc){
    int i = blockIdx.x*blockDim.x + threadIdx.x;
    if (i >= E) return;
    int s = e[i], d = e[E+i];
    atomicAdd(&degi[d], 1);
    if (s == d) atomicAdd(&selfc[d], 1);
}

__global__ void k_deg0_fin(const int* __restrict__ degi, const int* __restrict__ selfc,
                           float* dinv, float* fill, int n){
    int i = blockIdx.x*blockDim.x + threadIdx.x;
    if (i >= n) return;
    float f = (selfc[i] == 0) ? 2.0f : 0.0f;
    float deg = (float)degi[i] + f;
    dinv[i] = (deg > 0.f) ? 1.0f/sqrtf(deg) : 0.0f;
    fill[i] = f;
}

__global__ void k_bucket_fill(const int* __restrict__ e, int E, int* cnt, int* bucket){
    int i = blockIdx.x*blockDim.x + threadIdx.x;
    if (i >= E) return;
    int s = e[i], d = e[E+i];
    if (s == d) return;
    int p = atomicAdd(&cnt[s], 1);
    if (p < CAP) bucket[s*CAP + p] = d;
}

__global__ void k_set_inv(const int* __restrict__ perm, int* inv, int k){
    int r = blockIdx.x*blockDim.x + threadIdx.x;
    if (r < k) inv[perm[r]] = r;
}

__global__ void k_scatter_aug_inv(const int* __restrict__ e, int E, const int* __restrict__ inv,
                                  float* A, int k){
    int i = blockIdx.x*blockDim.x + threadIdx.x;
    if (i >= E) return;
    int s = e[i], d = e[E+i];
    if (s == d) return;
    int ir = inv[d], ic = inv[s];
    if (ir >= 0 && ic >= 0) atomicAdd(&A[(size_t)ir*k + ic], 2.0f);
}

__global__ void k_join_inv(const int* __restrict__ e, int E, const int* __restrict__ cnt,
                           const int* __restrict__ bucket, const int* __restrict__ inv,
                           float* A, int k){
    int i = blockIdx.x*blockDim.x + threadIdx.x;
    if (i >= E) return;
    int s2 = e[i], d2 = e[E+i];
    if (s2 == d2) return;
    int ic = inv[s2];
    if (ic < 0) return;
    int c = min(cnt[d2], CAP);
    const int* b = bucket + d2*CAP;
    for (int t = 0; t < c; t++){
        int d1 = b[t];
        if (d1 == s2) continue;
        int ir = inv[d1];
        if (ir >= 0) atomicAdd(&A[(size_t)ir*k + ic], 1.0f);
    }
}

// Z[d][:] += U[s][:] per edge; warp-per-edge
__global__ void k_spmm(const int* __restrict__ e, int E, const float* __restrict__ U,
                       float* Z, int F){
    int w = (blockIdx.x*blockDim.x + threadIdx.x) >> 5;
    int lane = threadIdx.x & 31;
    if (w >= E) return;
    int s = e[w], d = e[E+w];
    const float* ur = U + (size_t)s*F;
    float* zr = Z + (size_t)d*F;
    for (int f = lane; f < F; f += 32) atomicAdd(&zr[f], ur[f]);
}

// ---------------- dense helpers ----------------

// deg = rowsum(A) + fill (fill=2 where diag==0); dinv = 1/sqrt(deg)
__global__ void k_deg(const float* __restrict__ A, int n, float* dinv, float* fill){
    int row  = blockIdx.x*(blockDim.x >> 5) + (threadIdx.x >> 5);
    int lane = threadIdx.x & 31;
    if (row >= n) return;
    const float* r = A + (size_t)row*n;
    float s = 0.f;
    for (int j = lane; j < n; j += 32) s += r[j];
    #pragma unroll
    for (int o = 16; o; o >>= 1) s += __shfl_xor_sync(0xffffffffu, s, o);
    if (lane == 0){
        float f = (r[row] == 0.0f) ? 2.0f : 0.0f;
        float deg = s + f;
        dinv[row] = (deg > 0.f) ? 1.0f/sqrtf(deg) : 0.0f;
        fill[row] = f;
    }
}

// Vectorized GEMM, no guards: M%BM==0, N%BN==0, kc%16==0.
// NT = (BM/TM)*(BN/TN) threads. Writes raw tile to part + blockIdx.z*M*N.
template<int BM,int BN,int TM,int TN>
__global__ void k_gemm_f4(
    const float* __restrict__ A, const float* __restrict__ B, float* __restrict__ part,
    int M, int N, int K, int kc)
{
    const int BK = 16;
    const int NT = (BM/TM)*(BN/TN);
    __shared__ float As[BK][BM+4];
    __shared__ float Bs[BK][BN];
    int tid = threadIdx.x;
    int tx = tid % (BN/TN), ty = tid / (BN/TN);
    int bm = blockIdx.y*BM, bn = blockIdx.x*BN;
    int k0 = blockIdx.z*kc;
    float acc[TM][TN] = {};
    for (int kb = k0; kb < k0 + kc; kb += BK){
        #pragma unroll
        for (int q = 0; q < (BM*4)/NT; q++){
            int idx = tid + q*NT;
            int row = idx >> 2, c4 = (idx & 3) << 2;
            float4 v = *reinterpret_cast<const float4*>(&A[(size_t)(bm+row)*K + kb + c4]);
            As[c4+0][row] = v.x; As[c4+1][row] = v.y;
            As[c4+2][row] = v.z; As[c4+3][row] = v.w;
        }
        #pragma unroll
        for (int q = 0; q < (4*BN)/NT; q++){
            int idx = tid + q*NT;
            int row = idx/(BN/4), c4 = (idx % (BN/4)) << 2;
            *reinterpret_cast<float4*>(&Bs[row][c4]) =
                *reinterpret_cast<const float4*>(&B[(size_t)(kb+row)*N + bn + c4]);
        }
        __syncthreads();
        #pragma unroll
        for (int k = 0; k < BK; k++){
            float a[TM], b[TN];
            #pragma unroll
            for (int i = 0; i < TM; i += 4)
                *reinterpret_cast<float4*>(&a[i]) = *reinterpret_cast<const float4*>(&As[k][ty*TM + i]);
            #pragma unroll
            for (int j = 0; j < TN; j += 4)
                *reinterpret_cast<float4*>(&b[j]) = *reinterpret_cast<const float4*>(&Bs[k][tx*TN + j]);
            #pragma unroll
            for (int i = 0; i < TM; i++)
                #pragma unroll
                for (int j = 0; j < TN; j++)
                    acc[i][j] += a[i]*b[j];
        }
        __syncthreads();
    }
    float* out = part + (size_t)blockIdx.z*M*N;
    #pragma unroll
    for (int i = 0; i < TM; i++){
        int gm = bm + ty*TM + i;
        #pragma unroll
        for (int j = 0; j < TN; j += 4){
            int gn = bn + tx*TN + j;
            *reinterpret_cast<float4*>(&out[(size_t)gm*N + gn]) =
                *reinterpret_cast<const float4*>(&acc[i][j]);
        }
    }
}

// Fused skinny projection: U = dinv .* (x @ W), N<=64, K<=128, M%8==0.
__global__ __launch_bounds__(256) void k_xw(const float* __restrict__ x,
                                            const float* __restrict__ W,
                                            float* __restrict__ U,
                                            int M, int N, int K,
                                            const float* __restrict__ dinv){
    __shared__ float Ws[128][64];
    __shared__ float Xs[8][128];
    int tid = threadIdx.x;
    for (int idx = tid; idx < K*64; idx += 256){
        int k = idx >> 6, c = idx & 63;
        Ws[k][c] = (c < N) ? W[k*N + c] : 0.f;
    }
    int row0 = blockIdx.x*8;
    for (int idx = tid; idx < 8*K; idx += 256){
        int r = idx / K, k = idx - r*K;
        Xs[r][k] = x[(size_t)(row0 + r)*K + k];
    }
    __syncthreads();
    int warp = tid >> 5, lane = tid & 31;
    float a0 = 0.f, a1 = 0.f;
    for (int k = 0; k < K; k++){
        float xv = Xs[warp][k];
        a0 += xv * Ws[k][lane];
        a1 += xv * Ws[k][lane + 32];
    }
    int row = row0 + warp;
    float dv = dinv[row];
    if (lane < N)       U[(size_t)row*N + lane]      = dv * a0;
    if (lane + 32 < N)  U[(size_t)row*N + lane + 32] = dv * a1;
}

// Reduce SK partials (fixed order -> deterministic) + epilogue.
// flags: 4 zero diag, 8 scale dinv[m], 16 gcn epi, 32 relu
__global__ void k_redepi(float* out, const float* __restrict__ part, int SK, int M, int N,
                         int flags, const float* __restrict__ dinv, const float* __restrict__ fl,
                         const float* __restrict__ bias, const float* __restrict__ Uin)
{
    size_t idx = (size_t)blockIdx.x*blockDim.x + threadIdx.x;
    if (idx >= (size_t)M*N) return;
    int m = (int)(idx / N), n = (int)(idx % N);
    size_t MN = (size_t)M*N;
    float v = 0.f;
    for (int z = 0; z < SK; z++) v += part[z*MN + idx];
    if (flags & 16)      v = dinv[m]*(v + fl[m]*Uin[idx]) + bias[n];
    else if (flags & 8)  v *= dinv[m];
    if (flags & 32) v = fmaxf(v, 0.f);
    if ((flags & 4) && m == n) v = 0.f;
    out[idx] = v;
}

// ---------------- augment operand gathers (B = A + I) ----------------

__global__ void k_gather_rows(const float* __restrict__ A, int n, const int* __restrict__ perm,
                              float* Gr, int k){
    size_t t = (size_t)blockIdx.x*blockDim.x + threadIdx.x;
    size_t tot = (size_t)k*(n/4);
    if (t >= tot) return;
    int r = (int)(t / (n/4));
    int c4 = (int)(t % (n/4))*4;
    *reinterpret_cast<float4*>(&Gr[(size_t)r*n + c4]) =
        *reinterpret_cast<const float4*>(&A[(size_t)perm[r]*n + c4]);
}
__global__ void k_diag_r(float* Gr, int n, const int* __restrict__ perm, int k){
    int r = blockIdx.x*blockDim.x + threadIdx.x;
    if (r < k) Gr[(size_t)r*n + perm[r]] += 1.f;
}
__global__ void k_gather_cols(const float* __restrict__ A, int n, const int* __restrict__ perm,
                              float* Gc, int k){
    size_t t = (size_t)blockIdx.x*blockDim.x + threadIdx.x;
    if (t >= (size_t)n*k) return;
    int j = (int)(t / k), c = (int)(t % k);
    Gc[t] = A[(size_t)j*n + perm[c]];
}
__global__ void k_diag_c(float* Gc, const int* __restrict__ perm, int k){
    int c = blockIdx.x*blockDim.x + threadIdx.x;
    if (c < k) Gc[(size_t)perm[c]*k + c] += 1.f;
}

// ---------------- gcn epilogue (sparse path) ----------------

__global__ void k_gcn_epi(const float* Z, const float* U, const float* dinv, const float* fill,
                          const float* __restrict__ b, float* out, int n, int F, int relu){
    int idx = blockIdx.x*blockDim.x + threadIdx.x;
    if (idx >= n*F) return;
    int i = idx / F, f = idx % F;
    float v = dinv[i]*(Z[idx] + fill[i]*U[idx]) + b[f];
    if (relu) v = fmaxf(v, 0.f);
    out[idx] = v;
}

// ---------------- topk / gather / misc ----------------

__global__ void k_wnorm(const float* w, int F, float* out){
    __shared__ float sh[256];
    float s = 0.f;
    for (int i = threadIdx.x; i < F; i += 256) s += w[i]*w[i];
    sh[threadIdx.x] = s; __syncthreads();
    for (int o = 128; o; o >>= 1){
        if (threadIdx.x < o) sh[threadIdx.x] += sh[threadIdx.x + o];
        __syncthreads();
    }
    if (threadIdx.x == 0) out[0] = sqrtf(sh[0]);
}

__global__ void k_score(const float* x, int n, int F, const float* __restrict__ w,
                        const float* nrm, float* score){
    int i = blockIdx.x*blockDim.x + threadIdx.x;
    if (i >= n) return;
    const float* r = x + (size_t)i*F;
    float s = 0.f;
    for (int f = 0; f < F; f++) s += r[f]*w[f];
    score[i] = tanhf(s / nrm[0]);
}

// two-phase stable top-k (rank counting), matches jax.lax.top_k ordering.
// phase 1: partial rank counts over j-chunks; n % 256 == 0, gridDim.y divides n/256.
__global__ void k_topk_cnt(const float* __restrict__ s, int n, int* cnt){
    __shared__ float sj[256];
    int i = blockIdx.x*256 + threadIdx.x;
    float si = s[i];
    int chunk = n / gridDim.y;
    int j0 = blockIdx.y * chunk;
    int c = 0;
    for (int jb = j0; jb < j0 + chunk; jb += 256){
        sj[threadIdx.x] = s[jb + threadIdx.x];
        __syncthreads();
        #pragma unroll 8
        for (int t = 0; t < 256; t++){
            float v = sj[t]; int j = jb + t;
            c += (v > si) || (v == si && j < i);
        }
        __syncthreads();
    }
    atomicAdd(&cnt[i], c);
}
__global__ void k_topk_place(const float* __restrict__ s, const int* __restrict__ cnt,
                             int n, int k, int* idx, float* vals){
    int i = blockIdx.x*blockDim.x + threadIdx.x;
    if (i >= n) return;
    int c = cnt[i];
    if (c < k){ idx[c] = i; vals[c] = s[i]; }
}

__global__ void k_gather_x(const float* x, int F, const int* idx, const float* vals,
                           float* out, int k){
    int t = blockIdx.x*blockDim.x + threadIdx.x;
    if (t >= k*F) return;
    int r = t / F, f = t % F;
    out[t] = x[(size_t)idx[r]*F + f] * vals[r];
}

__global__ void k_concat_res(const float* res, int C, float* xcat, int n){
    int t = blockIdx.x*blockDim.x + threadIdx.x;
    int W = 2*C;
    if (t >= n*W) return;
    int r = t / W, f = t % W;
    xcat[t] = (f < C) ? res[(size_t)r*C + f] : 0.f;
}

__global__ void k_scatter_up(const float* x, int Fx, int C, const int* perm,
                             float* xcat, int nsmall){
    int t = blockIdx.x*blockDim.x + threadIdx.x;
    if (t >= nsmall*C) return;
    int r = t / C, f = t % C;
    xcat[(size_t)perm[r]*(2*C) + C + f] = x[(size_t)r*Fx + f];
}

__global__ void k_softmax(const float* z, float* out, int n, int C){
    int i = blockIdx.x*blockDim.x + threadIdx.x;
    if (i >= n) return;
    const float* r = z + (size_t)i*C;
    float m = -1e30f;
    for (int c = 0; c < C; c++) m = fmaxf(m, r[c]);
    float s = 0.f;
    for (int c = 0; c < C; c++) s += expf(r[c] - m);
    float inv = 1.0f/s;
    for (int c = 0; c < C; c++) out[(size_t)i*C + c] = expf(r[c] - m)*inv;
}

// ---------------- host orchestration ----------------

extern "C" void kernel_launch(void* const* d_in, const int* in_sizes, int n_in,
                              void* d_out, int out_size){
    const float* x_in = (const float*)d_in[0];
    const int*   eidx = (const int*)d_in[1];
    const float *Wd[5], *bd[5], *pv[4], *Wu[4], *bu[4];
    for (int i = 0; i < 5; i++){ Wd[i] = (const float*)d_in[2 + 2*i]; bd[i] = (const float*)d_in[3 + 2*i]; }
    for (int i = 0; i < 4; i++)  pv[i] = (const float*)d_in[12 + i];
    for (int i = 0; i < 4; i++){ Wu[i] = (const float*)d_in[16 + 2*i]; bu[i] = (const float*)d_in[17 + 2*i]; }
    const float* Wo = (const float*)d_in[24];
    const float* bo = (const float*)d_in[25];
    int E = in_sizes[1] / 2;

    float *pS,*pAs1,*pAs2,*pAs3,*pA4;
    float *px0,*px1,*px2,*px3,*px4,*pxg,*pxu,*pxcat,*pU,*pZ;
    float *pscore,*pvals,*pwn;
    float *pdinv[5], *pfill[5];
    int *pperm[4],*pcnt,*ptcnt,*pbucket,*pdegi,*pselfc,*pinv;
    cudaGetSymbolAddress((void**)&pS,    g_S);
    cudaGetSymbolAddress((void**)&pAs1,  g_As1);
    cudaGetSymbolAddress((void**)&pAs2,  g_As2);
    cudaGetSymbolAddress((void**)&pAs3,  g_As3);
    cudaGetSymbolAddress((void**)&pA4,   g_A4);
    cudaGetSymbolAddress((void**)&px0,   g_x0);
    cudaGetSymbolAddress((void**)&px1,   g_x1);
    cudaGetSymbolAddress((void**)&px2,   g_x2);
    cudaGetSymbolAddress((void**)&px3,   g_x3);
    cudaGetSymbolAddress((void**)&px4,   g_x4);
    cudaGetSymbolAddress((void**)&pxg,   g_xg);
    cudaGetSymbolAddress((void**)&pxu,   g_xu);
    cudaGetSymbolAddress((void**)&pxcat, g_xcat);
    cudaGetSymbolAddress((void**)&pU,    g_bU);
    cudaGetSymbolAddress((void**)&pZ,    g_bZ);
    cudaGetSymbolAddress((void**)&pdinv[0], g_dinv0); cudaGetSymbolAddress((void**)&pfill[0], g_fill0);
    cudaGetSymbolAddress((void**)&pdinv[1], g_dinv1); cudaGetSymbolAddress((void**)&pfill[1], g_fill1);
    cudaGetSymbolAddress((void**)&pdinv[2], g_dinv2); cudaGetSymbolAddress((void**)&pfill[2], g_fill2);
    cudaGetSymbolAddress((void**)&pdinv[3], g_dinv3); cudaGetSymbolAddress((void**)&pfill[3], g_fill3);
    cudaGetSymbolAddress((void**)&pdinv[4], g_dinv4); cudaGetSymbolAddress((void**)&pfill[4], g_fill4);
    cudaGetSymbolAddress((void**)&pscore, g_score);
    cudaGetSymbolAddress((void**)&pvals,  g_vals);
    cudaGetSymbolAddress((void**)&pwn,    g_wn);
    cudaGetSymbolAddress((void**)&pperm[0], g_perm0);
    cudaGetSymbolAddress((void**)&pperm[1], g_perm1);
    cudaGetSymbolAddress((void**)&pperm[2], g_perm2);
    cudaGetSymbolAddress((void**)&pperm[3], g_perm3);
    cudaGetSymbolAddress((void**)&pcnt,   g_cnt);
    cudaGetSymbolAddress((void**)&ptcnt,  g_tcnt);
    cudaGetSymbolAddress((void**)&pdegi,  g_degi);
    cudaGetSymbolAddress((void**)&pselfc, g_selfc);
    cudaGetSymbolAddress((void**)&pinv,   g_inv);
    cudaGetSymbolAddress((void**)&pbucket,g_bucket);

    float* pGr   = pS;             // up to 2M floats
    float* pGc   = pS + 4194304;   // up to 2M floats
    float* ppart = pS + 8388608;   // up to 4M floats (SK partials)

    auto g128 = [&](const float* A, const float* B, int M, int N, int K, int SK){
        dim3 g(N/128, M/128, SK);
        k_gemm_f4<128,128,8,8><<<g,256>>>(A,B,ppart,M,N,K,K/SK);
    };
    auto g64 = [&](const float* A, const float* B, int M, int N, int K, int SK){
        dim3 g(N/64, M/64, SK);
        k_gemm_f4<64,64,8,8><<<g,64>>>(A,B,ppart,M,N,K,K/SK);
    };
    auto red = [&](float* out, int SK, int M, int N, int flags,
                   const float* dv, const float* fl, const float* bias, const float* Uin){
        size_t tot = (size_t)M*N;
        k_redepi<<<(unsigned)((tot + 255)/256), 256>>>(out, ppart, SK, M, N, flags, dv, fl, bias, Uin);
    };
    auto topk = [&](const float* x, int n, int F, const float* w, int k, int* perm){
        k_wnorm<<<1, 256>>>(w, F, pwn);
        k_score<<<(n + 255)/256, 256>>>(x, n, F, w, pwn, pscore);
        cudaMemsetAsync(ptcnt, 0, n*sizeof(int), 0);
        int chy = n/256 < 8 ? n/256 : 8;
        dim3 gr(n/256, chy);
        k_topk_cnt<<<gr, 256>>>(pscore, n, ptcnt);
        k_topk_place<<<(n + 255)/256, 256>>>(pscore, ptcnt, n, k, perm, pvals);
    };
    // dense GCN: U = dinv*(xW); out = dinv*(A@U + fill*U) + b [relu]
    auto gcnD = [&](const float* A, int n, const float* dv, const float* fl,
                    const float* x, int fin, const float* W, const float* b,
                    int fout, float* out, bool relu){
        if (fout <= 64 && fin <= 128){
            k_xw<<<n/8, 256>>>(x, W, pU, n, fout, fin, dv);
        } else {
            g64(x, W, n, fout, fin, 4);
            red(pU, 4, n, fout, 8, dv, nullptr, nullptr, nullptr);
        }
        g64(A, pU, n, fout, n, 16);
        red(out, 16, n, fout, 16 | (relu ? 32 : 0), dv, fl, b, pU);
    };
    // sparse level-0 GCN (fin<=128, fout<=64 always here)
    auto gcn0 = [&](const float* x, int fin, const float* W, const float* b,
                    int fout, float* out, bool relu){
        k_xw<<<4096/8, 256>>>(x, W, pU, 4096, fout, fin, pdinv[0]);
        cudaMemsetAsync(pZ, 0, (size_t)4096*fout*sizeof(float), 0);
        k_spmm<<<(E*32 + 255)/256, 256>>>(eidx, E, pU, pZ, fout);
        int tot = 4096*fout;
        k_gcn_epi<<<(tot + 255)/256, 256>>>(pZ, pU, pdinv[0], pfill[0], b, out, 4096, fout, relu ? 1 : 0);
    };
    // pooled augment: Adst(k x k) = (Asrc+I)[perm,:] @ (Asrc+I)[:,perm], zero diag
    auto aug = [&](const float* Asrc, int n, const int* perm, int k, float* Adst){
        size_t rt = (size_t)k*(n/4);
        k_gather_rows<<<(unsigned)((rt + 255)/256), 256>>>(Asrc, n, perm, pGr, k);
        k_diag_r<<<(k + 255)/256, 256>>>(pGr, n, perm, k);
        size_t ct = (size_t)n*k;
        k_gather_cols<<<(unsigned)((ct + 255)/256), 256>>>(Asrc, n, perm, pGc, k);
        k_diag_c<<<(k + 255)/256, 256>>>(pGc, perm, k);
        int SK;
        if (k >= 1024){ SK = 4; g128(pGr, pGc, k, k, n, SK); }
        else if (k >= 512){ SK = 4; g64(pGr, pGc, k, k, n, SK); }
        else { SK = 8; g64(pGr, pGc, k, k, n, SK); }
        red(Adst, SK, k, k, 4, nullptr, nullptr, nullptr, nullptr);
    };

    // ---- level-0 degrees + buckets from edge list ----
    cudaMemsetAsync(pdegi, 0, 4096*sizeof(int), 0);
    cudaMemsetAsync(pselfc, 0, 4096*sizeof(int), 0);
    k_edge_stats<<<(E + 255)/256, 256>>>(eidx, E, pdegi, pselfc);
    k_deg0_fin<<<(4096 + 255)/256, 256>>>(pdegi, pselfc, pdinv[0], pfill[0], 4096);
    cudaMemsetAsync(pcnt, 0, 4096*sizeof(int), 0);
    k_bucket_fill<<<(E + 255)/256, 256>>>(eidx, E, pcnt, pbucket);

    // ---- down level 0 (sparse) ----
    gcn0(x_in, 128, Wd[0], bd[0], 32, px0, true);

    // ---- pool to 2048; build As1 directly via inverse perm (sparse join) ----
    topk(px0, 4096, 32, pv[0], 2048, pperm[0]);
    k_gather_x<<<(2048*32 + 255)/256, 256>>>(px0, 32, pperm[0], pvals, pxg, 2048);
    cudaMemsetAsync(pAs1, 0, (size_t)2048*2048*sizeof(float), 0);
    cudaMemsetAsync(pinv, 0xFF, 4096*sizeof(int), 0);
    k_set_inv<<<(2048 + 255)/256, 256>>>(pperm[0], pinv, 2048);
    k_scatter_aug_inv<<<(E + 255)/256, 256>>>(eidx, E, pinv, pAs1, 2048);
    k_join_inv<<<(E + 255)/256, 256>>>(eidx, E, pcnt, pbucket, pinv, pAs1, 2048);
    k_deg<<<(2048 + 7)/8, 256>>>(pAs1, 2048, pdinv[1], pfill[1]);
    gcnD(pAs1, 2048, pdinv[1], pfill[1], pxg, 32, Wd[1], bd[1], 64, px1, true);

    // ---- level 2: pooled augment (1024x1024x2048), GCN ----
    topk(px1, 2048, 64, pv[1], 1024, pperm[1]);
    aug(pAs1, 2048, pperm[1], 1024, pAs2);
    k_gather_x<<<(1024*64 + 255)/256, 256>>>(px1, 64, pperm[1], pvals, pxg, 1024);
    k_deg<<<(1024 + 7)/8, 256>>>(pAs2, 1024, pdinv[2], pfill[2]);
    gcnD(pAs2, 1024, pdinv[2], pfill[2], pxg, 64, Wd[2], bd[2], 128, px2, true);

    // ---- level 3: pooled augment (512x512x1024), GCN ----
    topk(px2, 1024, 128, pv[2], 512, pperm[2]);
    aug(pAs2, 1024, pperm[2], 512, pAs3);
    k_gather_x<<<(512*128 + 255)/256, 256>>>(px2, 128, pperm[2], pvals, pxg, 512);
    k_deg<<<(512 + 7)/8, 256>>>(pAs3, 512, pdinv[3], pfill[3]);
    gcnD(pAs3, 512, pdinv[3], pfill[3], pxg, 128, Wd[3], bd[3], 256, px3, true);

    // ---- level 4: pooled augment (256x256x512), GCN ----
    topk(px3, 512, 256, pv[3], 256, pperm[3]);
    aug(pAs3, 512, pperm[3], 256, pA4);
    k_gather_x<<<(256*256 + 255)/256, 256>>>(px3, 256, pperm[3], pvals, pxg, 256);
    k_deg<<<(256 + 7)/8, 256>>>(pA4, 256, pdinv[4], pfill[4]);
    gcnD(pA4, 256, pdinv[4], pfill[4], pxg, 256, Wd[4], bd[4], 512, px4, true);

    // ---- up path ----
    k_concat_res<<<(512*512 + 255)/256, 256>>>(px3, 256, pxcat, 512);
    k_scatter_up<<<(256*256 + 255)/256, 256>>>(px4, 512, 256, pperm[3], pxcat, 256);
    gcnD(pAs3, 512, pdinv[3], pfill[3], pxcat, 512, Wu[0], bu[0], 256, pxu, true);

    k_concat_res<<<(1024*256 + 255)/256, 256>>>(px2, 128, pxcat, 1024);
    k_scatter_up<<<(512*128 + 255)/256, 256>>>(pxu, 256, 128, pperm[2], pxcat, 512);
    gcnD(pAs2, 1024, pdinv[2], pfill[2], pxcat, 256, Wu[1], bu[1], 128, pxu, true);

    k_concat_res<<<(2048*128 + 255)/256, 256>>>(px1, 64, pxcat, 2048);
    k_scatter_up<<<(1024*64 + 255)/256, 256>>>(pxu, 128, 64, pperm[1], pxcat, 1024);
    gcnD(pAs1, 2048, pdinv[1], pfill[1], pxcat, 128, Wu[2], bu[2], 64, pxu, true);

    k_concat_res<<<(4096*64 + 255)/256, 256>>>(px0, 32, pxcat, 4096);
    k_scatter_up<<<(2048*32 + 255)/256, 256>>>(pxu, 64, 32, pperm[0], pxcat, 2048);
    gcn0(pxcat, 64, Wu[3], bu[3], 32, pxu, false);

    // ---- final GCN (sparse) + softmax ----
    gcn0(pxu, 32, Wo, bo, 37, pxcat, false);
    k_softmax<<<(4096 + 255)/256, 256>>>(pxcat, (float*)d_out, 4096, 37);
}

// round 11
// speedup vs baseline: 8.0430x; 1.0970x over previous
#include <cuda_runtime.h>
#include <cuda_bf16.h>
#include <mma.h>
#include <math.h>

using namespace nvcuda;

#define CAP 192

// ---------------- static device scratch (no allocation allowed) ----------------
__device__ float g_S[(size_t)4096*4096];      // byte layout: [0,16M) Gr f32 | [16,32M) Gc f32 | [32,48M) part | [48,56M) A1b bf16 | [56,60M) Grb | [60,64M) Gcb
__device__ float g_As1[(size_t)2048*2048];
__device__ float g_As2[(size_t)1024*1024];
__device__ float g_As3[(size_t)512*512];
__device__ float g_A4[(size_t)256*256];
__device__ float g_x0[4096*32];
__device__ float g_x1[2048*64];
__device__ float g_x2[1024*128];
__device__ float g_x3[512*256];
__device__ float g_x4[256*512];
__device__ float g_xg[2048*64];
__device__ float g_xu[4096*64];
__device__ float g_xcat[4096*64];
__device__ float g_bU[4096*64];
__device__ float g_bZ[4096*64];
__device__ __nv_bfloat16 g_Uh[2048*64], g_Ul[2048*64], g_Ul2[2048*64];
__device__ float g_dinv0[4096], g_fill0[4096];
__device__ float g_dinv1[2048], g_fill1[2048];
__device__ float g_dinv2[1024], g_fill2[1024];
__device__ float g_dinv3[512],  g_fill3[512];
__device__ float g_dinv4[256],  g_fill4[256];
__device__ float g_score[4096];
__device__ float g_vals[4096];
__device__ float g_wn[1];
__device__ int   g_perm0[2048];
__device__ int   g_perm1[1024];
__device__ int   g_perm2[512];
__device__ int   g_perm3[256];
__device__ int   g_cnt[4096];
__device__ int   g_tcnt[4096];
__device__ int   g_degi[4096];
__device__ int   g_selfc[4096];
__device__ int   g_inv[4096];
__device__ int   g_bucket[4096*CAP];

// ---------------- sparse level-0 kernels ----------------

__global__ void k_edge_stats(const int* __restrict__ e, int E, int* degi, int* selfc){
    int i = blockIdx.x*blockDim.x + threadIdx.x;
    if (i >= E) return;
    int s = e[i], d = e[E+i];
    atomicAdd(&degi[d], 1);
    if (s == d) atomicAdd(&selfc[d], 1);
}

__global__ void k_deg0_fin(const int* __restrict__ degi, const int* __restrict__ selfc,
                           float* dinv, float* fill, int n){
    int i = blockIdx.x*blockDim.x + threadIdx.x;
    if (i >= n) return;
    float f = (selfc[i] == 0) ? 2.0f : 0.0f;
    float deg = (float)degi[i] + f;
    dinv[i] = (deg > 0.f) ? 1.0f/sqrtf(deg) : 0.0f;
    fill[i] = f;
}

__global__ void k_bucket_fill(const int* __restrict__ e, int E, int* cnt, int* bucket){
    int i = blockIdx.x*blockDim.x + threadIdx.x;
    if (i >= E) return;
    int s = e[i], d = e[E+i];
    if (s == d) return;
    int p = atomicAdd(&cnt[s], 1);
    if (p < CAP) bucket[s*CAP + p] = d;
}

__global__ void k_set_inv(const int* __restrict__ perm, int* inv, int k){
    int r = blockIdx.x*blockDim.x + threadIdx.x;
    if (r < k) inv[perm[r]] = r;
}

__global__ void k_scatter_aug_inv(const int* __restrict__ e, int E, const int* __restrict__ inv,
                                  float* A, int k){
    int i = blockIdx.x*blockDim.x + threadIdx.x;
    if (i >= E) return;
    int s = e[i], d = e[E+i];
    if (s == d) return;
    int ir = inv[d], ic = inv[s];
    if (ir >= 0 && ic >= 0) atomicAdd(&A[(size_t)ir*k + ic], 2.0f);
}

__global__ void k_join_inv(const int* __restrict__ e, int E, const int* __restrict__ cnt,
                           const int* __restrict__ bucket, const int* __restrict__ inv,
                           float* A, int k){
    int i = blockIdx.x*blockDim.x + threadIdx.x;
    if (i >= E) return;
    int s2 = e[i], d2 = e[E+i];
    if (s2 == d2) return;
    int ic = inv[s2];
    if (ic < 0) return;
    int c = min(cnt[d2], CAP);
    const int* b = bucket + d2*CAP;
    for (int t = 0; t < c; t++){
        int d1 = b[t];
        if (d1 == s2) continue;
        int ir = inv[d1];
        if (ir >= 0) atomicAdd(&A[(size_t)ir*k + ic], 1.0f);
    }
}

// Z[d][:] += U[s][:] per edge; warp-per-edge
__global__ void k_spmm(const int* __restrict__ e, int E, const float* __restrict__ U,
                       float* Z, int F){
    int w = (blockIdx.x*blockDim.x + threadIdx.x) >> 5;
    int lane = threadIdx.x & 31;
    if (w >= E) return;
    int s = e[w], d = e[E+w];
    const float* ur = U + (size_t)s*F;
    float* zr = Z + (size_t)d*F;
    for (int f = lane; f < F; f += 32) atomicAdd(&zr[f], ur[f]);
}

// ---------------- dense helpers ----------------

__global__ void k_deg(const float* __restrict__ A, int n, float* dinv, float* fill){
    int row  = blockIdx.x*(blockDim.x >> 5) + (threadIdx.x >> 5);
    int lane = threadIdx.x & 31;
    if (row >= n) return;
    const float* r = A + (size_t)row*n;
    float s = 0.f;
    for (int j = lane; j < n; j += 32) s += r[j];
    #pragma unroll
    for (int o = 16; o; o >>= 1) s += __shfl_xor_sync(0xffffffffu, s, o);
    if (lane == 0){
        float f = (r[row] == 0.0f) ? 2.0f : 0.0f;
        float deg = s + f;
        dinv[row] = (deg > 0.f) ? 1.0f/sqrtf(deg) : 0.0f;
        fill[row] = f;
    }
}

// Vectorized fp32 SIMT GEMM (unchanged from R10)
template<int BM,int BN,int TM,int TN>
__global__ void k_gemm_f4(
    const float* __restrict__ A, const float* __restrict__ B, float* __restrict__ part,
    int M, int N, int K, int kc)
{
    const int BK = 16;
    const int NT = (BM/TM)*(BN/TN);
    __shared__ float As[BK][BM+4];
    __shared__ float Bs[BK][BN];
    int tid = threadIdx.x;
    int tx = tid % (BN/TN), ty = tid / (BN/TN);
    int bm = blockIdx.y*BM, bn = blockIdx.x*BN;
    int k0 = blockIdx.z*kc;
    float acc[TM][TN] = {};
    for (int kb = k0; kb < k0 + kc; kb += BK){
        #pragma unroll
        for (int q = 0; q < (BM*4)/NT; q++){
            int idx = tid + q*NT;
            int row = idx >> 2, c4 = (idx & 3) << 2;
            float4 v = *reinterpret_cast<const float4*>(&A[(size_t)(bm+row)*K + kb + c4]);
            As[c4+0][row] = v.x; As[c4+1][row] = v.y;
            As[c4+2][row] = v.z; As[c4+3][row] = v.w;
        }
        #pragma unroll
        for (int q = 0; q < (4*BN)/NT; q++){
            int idx = tid + q*NT;
            int row = idx/(BN/4), c4 = (idx % (BN/4)) << 2;
            *reinterpret_cast<float4*>(&Bs[row][c4]) =
                *reinterpret_cast<const float4*>(&B[(size_t)(kb+row)*N + bn + c4]);
        }
        __syncthreads();
        #pragma unroll
        for (int k = 0; k < BK; k++){
            float a[TM], b[TN];
            #pragma unroll
            for (int i = 0; i < TM; i += 4)
                *reinterpret_cast<float4*>(&a[i]) = *reinterpret_cast<const float4*>(&As[k][ty*TM + i]);
            #pragma unroll
            for (int j = 0; j < TN; j += 4)
                *reinterpret_cast<float4*>(&b[j]) = *reinterpret_cast<const float4*>(&Bs[k][tx*TN + j]);
            #pragma unroll
            for (int i = 0; i < TM; i++)
                #pragma unroll
                for (int j = 0; j < TN; j++)
                    acc[i][j] += a[i]*b[j];
        }
        __syncthreads();
    }
    float* out = part + (size_t)blockIdx.z*M*N;
    #pragma unroll
    for (int i = 0; i < TM; i++){
        int gm = bm + ty*TM + i;
        #pragma unroll
        for (int j = 0; j < TN; j += 4){
            int gn = bn + tx*TN + j;
            *reinterpret_cast<float4*>(&out[(size_t)gm*N + gn]) =
                *reinterpret_cast<const float4*>(&acc[i][j]);
        }
    }
}

// bf16 WMMA GEMM: out(part+z*M*N) = [acc?load:0] + A@B over K-range [z*kc,(z+1)*kc).
// M%64==0, N%64==0, kc%32==0, K%8==0, N%8==0. 128 threads, 4 warps (2x2 of 32x32).
__global__ void k_wmma(const __nv_bfloat16* __restrict__ A, const __nv_bfloat16* __restrict__ B,
                       float* __restrict__ out, int M, int N, int K, int kc, int acc)
{
    __shared__ __nv_bfloat16 As[64][40];
    __shared__ __nv_bfloat16 Bs[32][72];
    int tid = threadIdx.x;
    int warp = tid >> 5;
    int wr = warp >> 1, wc = warp & 1;
    int bm = blockIdx.y*64, bn = blockIdx.x*64;
    float* o = out + (size_t)blockIdx.z*M*N;

    wmma::fragment<wmma::accumulator, 16,16,16, float> fc[2][2];
    #pragma unroll
    for (int i = 0; i < 2; i++)
        #pragma unroll
        for (int j = 0; j < 2; j++){
            if (acc)
                wmma::load_matrix_sync(fc[i][j],
                    &o[(size_t)(bm + wr*32 + i*16)*N + bn + wc*32 + j*16], N, wmma::mem_row_major);
            else
                wmma::fill_fragment(fc[i][j], 0.0f);
        }

    int k0 = blockIdx.z*kc;
    for (int kb = k0; kb < k0 + kc; kb += 32){
        #pragma unroll
        for (int q = 0; q < 2; q++){
            int idx = tid + q*128;
            int row = idx >> 2, c8 = (idx & 3) << 3;
            *reinterpret_cast<uint4*>(&As[row][c8]) =
                *reinterpret_cast<const uint4*>(&A[(size_t)(bm+row)*K + kb + c8]);
        }
        #pragma unroll
        for (int q = 0; q < 2; q++){
            int idx = tid + q*128;
            int row = idx >> 3, c8 = (idx & 7) << 3;
            *reinterpret_cast<uint4*>(&Bs[row][c8]) =
                *reinterpret_cast<const uint4*>(&B[(size_t)(kb+row)*N + bn + c8]);
        }
        __syncthreads();
        #pragma unroll
        for (int kf = 0; kf < 2; kf++){
            wmma::fragment<wmma::matrix_a, 16,16,16, __nv_bfloat16, wmma::row_major> fa[2];
            wmma::fragment<wmma::matrix_b, 16,16,16, __nv_bfloat16, wmma::row_major> fb[2];
            #pragma unroll
            for (int i = 0; i < 2; i++)
                wmma::load_matrix_sync(fa[i], &As[wr*32 + i*16][kf*16], 40);
            #pragma unroll
            for (int j = 0; j < 2; j++)
                wmma::load_matrix_sync(fb[j], &Bs[kf*16][wc*32 + j*16], 72);
            #pragma unroll
            for (int i = 0; i < 2; i++)
                #pragma unroll
                for (int j = 0; j < 2; j++)
                    wmma::mma_sync(fc[i][j], fa[i], fb[j], fc[i][j]);
        }
        __syncthreads();
    }
    #pragma unroll
    for (int i = 0; i < 2; i++)
        #pragma unroll
        for (int j = 0; j < 2; j++)
            wmma::store_matrix_sync(&o[(size_t)(bm + wr*32 + i*16)*N + bn + wc*32 + j*16],
                                    fc[i][j], N, wmma::mem_row_major);
}

// Fused skinny projection: U = dinv .* (x @ W), N<=64, K<=128, M%8==0.
__global__ __launch_bounds__(256) void k_xw(const float* __restrict__ x,
                                            const float* __restrict__ W,
                                            float* __restrict__ U,
                                            int M, int N, int K,
                                            const float* __restrict__ dinv){
    __shared__ float Ws[128][64];
    __shared__ float Xs[8][128];
    int tid = threadIdx.x;
    for (int idx = tid; idx < K*64; idx += 256){
        int k = idx >> 6, c = idx & 63;
        Ws[k][c] = (c < N) ? W[k*N + c] : 0.f;
    }
    int row0 = blockIdx.x*8;
    for (int idx = tid; idx < 8*K; idx += 256){
        int r = idx / K, k = idx - r*K;
        Xs[r][k] = x[(size_t)(row0 + r)*K + k];
    }
    __syncthreads();
    int warp = tid >> 5, lane = tid & 31;
    float a0 = 0.f, a1 = 0.f;
    for (int k = 0; k < K; k++){
        float xv = Xs[warp][k];
        a0 += xv * Ws[k][lane];
        a1 += xv * Ws[k][lane + 32];
    }
    int row = row0 + warp;
    float dv = dinv[row];
    if (lane < N)       U[(size_t)row*N + lane]      = dv * a0;
    if (lane + 32 < N)  U[(size_t)row*N + lane + 32] = dv * a1;
}

// Reduce SK partials (fixed order -> deterministic) + epilogue.
// flags: 4 zero diag, 8 scale dinv[m], 16 gcn epi, 32 relu
__global__ void k_redepi(float* out, const float* __restrict__ part, int SK, int M, int N,
                         int flags, const float* __restrict__ dinv, const float* __restrict__ fl,
                         const float* __restrict__ bias, const float* __restrict__ Uin)
{
    size_t idx = (size_t)blockIdx.x*blockDim.x + threadIdx.x;
    if (idx >= (size_t)M*N) return;
    int m = (int)(idx / N), n = (int)(idx % N);
    size_t MN = (size_t)M*N;
    float v = 0.f;
    for (int z = 0; z < SK; z++) v += part[z*MN + idx];
    if (flags & 16)      v = dinv[m]*(v + fl[m]*Uin[idx]) + bias[n];
    else if (flags & 8)  v *= dinv[m];
    if (flags & 32) v = fmaxf(v, 0.f);
    if ((flags & 4) && m == n) v = 0.f;
    out[idx] = v;
}

// ---------------- conversion kernels ----------------

__global__ void k_f2b(const float* __restrict__ in, __nv_bfloat16* __restrict__ out, size_t n){
    size_t i = (size_t)blockIdx.x*blockDim.x + threadIdx.x;
    if (i < n) out[i] = __float2bfloat16(in[i]);
}

// 3-term bf16 split: U = h + l + l2 (covers 24 mantissa bits -> fp32-exact)
__global__ void k_split3(const float* __restrict__ U, __nv_bfloat16* h, __nv_bfloat16* l,
                         __nv_bfloat16* l2, int n){
    int i = blockIdx.x*blockDim.x + threadIdx.x;
    if (i >= n) return;
    float v = U[i];
    __nv_bfloat16 a = __float2bfloat16(v);
    float r = v - __bfloat162float(a);
    __nv_bfloat16 b = __float2bfloat16(r);
    float r2 = r - __bfloat162float(b);
    h[i] = a; l[i] = b; l2[i] = __float2bfloat16(r2);
}

// ---------------- augment operand gathers ----------------

// fp32 versions (B = A + I), for small levels
__global__ void k_gather_rows(const float* __restrict__ A, int n, const int* __restrict__ perm,
                              float* Gr, int k){
    size_t t = (size_t)blockIdx.x*blockDim.x + threadIdx.x;
    size_t tot = (size_t)k*(n/4);
    if (t >= tot) return;
    int r = (int)(t / (n/4));
    int c4 = (int)(t % (n/4))*4;
    *reinterpret_cast<float4*>(&Gr[(size_t)r*n + c4]) =
        *reinterpret_cast<const float4*>(&A[(size_t)perm[r]*n + c4]);
}
__global__ void k_diag_r(float* Gr, int n, const int* __restrict__ perm, int k){
    int r = blockIdx.x*blockDim.x + threadIdx.x;
    if (r < k) Gr[(size_t)r*n + perm[r]] += 1.f;
}
__global__ void k_gather_cols(const float* __restrict__ A, int n, const int* __restrict__ perm,
                              float* Gc, int k){
    size_t t = (size_t)blockIdx.x*blockDim.x + threadIdx.x;
    if (t >= (size_t)n*k) return;
    int j = (int)(t / k), c = (int)(t % k);
    Gc[t] = A[(size_t)j*n + perm[c]];
}
__global__ void k_diag_c(float* Gc, const int* __restrict__ perm, int k){
    int c = blockIdx.x*blockDim.x + threadIdx.x;
    if (c < k) Gc[(size_t)perm[c]*k + c] += 1.f;
}

// bf16 versions with +I folded in (exact: level-1 adjacency entries are small ints)
__global__ void k_gather_rows_bf(const float* __restrict__ A, int n, const int* __restrict__ perm,
                                 __nv_bfloat16* Gr, int k){
    size_t t = (size_t)blockIdx.x*blockDim.x + threadIdx.x;
    if (t >= (size_t)k*n) return;
    int r = (int)(t / n), c = (int)(t % n);
    int pr = perm[r];
    float v = A[(size_t)pr*n + c] + ((c == pr) ? 1.f : 0.f);
    Gr[t] = __float2bfloat16(v);
}
__global__ void k_gather_cols_bf(const float* __restrict__ A, int n, const int* __restrict__ perm,
                                 __nv_bfloat16* Gc, int k){
    size_t t = (size_t)blockIdx.x*blockDim.x + threadIdx.x;
    if (t >= (size_t)n*k) return;
    int j = (int)(t / k), c = (int)(t % k);
    int pc = perm[c];
    float v = A[(size_t)j*n + pc] + ((j == pc) ? 1.f : 0.f);
    Gc[t] = __float2bfloat16(v);
}

// ---------------- gcn epilogue (sparse path) ----------------

__global__ void k_gcn_epi(const float* Z, const float* U, const float* dinv, const float* fill,
                          const float* __restrict__ b, float* out, int n, int F, int relu){
    int idx = blockIdx.x*blockDim.x + threadIdx.x;
    if (idx >= n*F) return;
    int i = idx / F, f = idx % F;
    float v = dinv[i]*(Z[idx] + fill[i]*U[idx]) + b[f];
    if (relu) v = fmaxf(v, 0.f);
    out[idx] = v;
}

// ---------------- topk / gather / misc ----------------

__global__ void k_wnorm(const float* w, int F, float* out){
    __shared__ float sh[256];
    float s = 0.f;
    for (int i = threadIdx.x; i < F; i += 256) s += w[i]*w[i];
    sh[threadIdx.x] = s; __syncthreads();
    for (int o = 128; o; o >>= 1){
        if (threadIdx.x < o) sh[threadIdx.x] += sh[threadIdx.x + o];
        __syncthreads();
    }
    if (threadIdx.x == 0) out[0] = sqrtf(sh[0]);
}

__global__ void k_score(const float* x, int n, int F, const float* __restrict__ w,
                        const float* nrm, float* score){
    int i = blockIdx.x*blockDim.x + threadIdx.x;
    if (i >= n) return;
    const float* r = x + (size_t)i*F;
    float s = 0.f;
    for (int f = 0; f < F; f++) s += r[f]*w[f];
    score[i] = tanhf(s / nrm[0]);
}

__global__ void k_topk_cnt(const float* __restrict__ s, int n, int* cnt){
    __shared__ float sj[256];
    int i = blockIdx.x*256 + threadIdx.x;
    float si = s[i];
    int chunk = n / gridDim.y;
    int j0 = blockIdx.y * chunk;
    int c = 0;
    for (int jb = j0; jb < j0 + chunk; jb += 256){
        sj[threadIdx.x] = s[jb + threadIdx.x];
        __syncthreads();
        #pragma unroll 8
        for (int t = 0; t < 256; t++){
            float v = sj[t]; int j = jb + t;
            c += (v > si) || (v == si && j < i);
        }
        __syncthreads();
    }
    atomicAdd(&cnt[i], c);
}
__global__ void k_topk_place(const float* __restrict__ s, const int* __restrict__ cnt,
                             int n, int k, int* idx, float* vals){
    int i = blockIdx.x*blockDim.x + threadIdx.x;
    if (i >= n) return;
    int c = cnt[i];
    if (c < k){ idx[c] = i; vals[c] = s[i]; }
}

__global__ void k_gather_x(const float* x, int F, const int* idx, const float* vals,
                           float* out, int k){
    int t = blockIdx.x*blockDim.x + threadIdx.x;
    if (t >= k*F) return;
    int r = t / F, f = t % F;
    out[t] = x[(size_t)idx[r]*F + f] * vals[r];
}

__global__ void k_concat_res(const float* res, int C, float* xcat, int n){
    int t = blockIdx.x*blockDim.x + threadIdx.x;
    int W = 2*C;
    if (t >= n*W) return;
    int r = t / W, f = t % W;
    xcat[t] = (f < C) ? res[(size_t)r*C + f] : 0.f;
}

__global__ void k_scatter_up(const float* x, int Fx, int C, const int* perm,
                             float* xcat, int nsmall){
    int t = blockIdx.x*blockDim.x + threadIdx.x;
    if (t >= nsmall*C) return;
    int r = t / C, f = t % C;
    xcat[(size_t)perm[r]*(2*C) + C + f] = x[(size_t)r*Fx + f];
}

__global__ void k_softmax(const float* z, float* out, int n, int C){
    int i = blockIdx.x*blockDim.x + threadIdx.x;
    if (i >= n) return;
    const float* r = z + (size_t)i*C;
    float m = -1e30f;
    for (int c = 0; c < C; c++) m = fmaxf(m, r[c]);
    float s = 0.f;
    for (int c = 0; c < C; c++) s += expf(r[c] - m);
    float inv = 1.0f/s;
    for (int c = 0; c < C; c++) out[(size_t)i*C + c] = expf(r[c] - m)*inv;
}

// ---------------- host orchestration ----------------

extern "C" void kernel_launch(void* const* d_in, const int* in_sizes, int n_in,
                              void* d_out, int out_size){
    const float* x_in = (const float*)d_in[0];
    const int*   eidx = (const int*)d_in[1];
    const float *Wd[5], *bd[5], *pv[4], *Wu[4], *bu[4];
    for (int i = 0; i < 5; i++){ Wd[i] = (const float*)d_in[2 + 2*i]; bd[i] = (const float*)d_in[3 + 2*i]; }
    for (int i = 0; i < 4; i++)  pv[i] = (const float*)d_in[12 + i];
    for (int i = 0; i < 4; i++){ Wu[i] = (const float*)d_in[16 + 2*i]; bu[i] = (const float*)d_in[17 + 2*i]; }
    const float* Wo = (const float*)d_in[24];
    const float* bo = (const float*)d_in[25];
    int E = in_sizes[1] / 2;

    float *pS,*pAs1,*pAs2,*pAs3,*pA4;
    float *px0,*px1,*px2,*px3,*px4,*pxg,*pxu,*pxcat,*pU,*pZ;
    float *pscore,*pvals,*pwn;
    float *pdinv[5], *pfill[5];
    __nv_bfloat16 *pUh,*pUl,*pUl2;
    int *pperm[4],*pcnt,*ptcnt,*pbucket,*pdegi,*pselfc,*pinv;
    cudaGetSymbolAddress((void**)&pS,    g_S);
    cudaGetSymbolAddress((void**)&pAs1,  g_As1);
    cudaGetSymbolAddress((void**)&pAs2,  g_As2);
    cudaGetSymbolAddress((void**)&pAs3,  g_As3);
    cudaGetSymbolAddress((void**)&pA4,   g_A4);
    cudaGetSymbolAddress((void**)&px0,   g_x0);
    cudaGetSymbolAddress((void**)&px1,   g_x1);
    cudaGetSymbolAddress((void**)&px2,   g_x2);
    cudaGetSymbolAddress((void**)&px3,   g_x3);
    cudaGetSymbolAddress((void**)&px4,   g_x4);
    cudaGetSymbolAddress((void**)&pxg,   g_xg);
    cudaGetSymbolAddress((void**)&pxu,   g_xu);
    cudaGetSymbolAddress((void**)&pxcat, g_xcat);
    cudaGetSymbolAddress((void**)&pU,    g_bU);
    cudaGetSymbolAddress((void**)&pZ,    g_bZ);
    cudaGetSymbolAddress((void**)&pUh,   g_Uh);
    cudaGetSymbolAddress((void**)&pUl,   g_Ul);
    cudaGetSymbolAddress((void**)&pUl2,  g_Ul2);
    cudaGetSymbolAddress((void**)&pdinv[0], g_dinv0); cudaGetSymbolAddress((void**)&pfill[0], g_fill0);
    cudaGetSymbolAddress((void**)&pdinv[1], g_dinv1); cudaGetSymbolAddress((void**)&pfill[1], g_fill1);
    cudaGetSymbolAddress((void**)&pdinv[2], g_dinv2); cudaGetSymbolAddress((void**)&pfill[2], g_fill2);
    cudaGetSymbolAddress((void**)&pdinv[3], g_dinv3); cudaGetSymbolAddress((void**)&pfill[3], g_fill3);
    cudaGetSymbolAddress((void**)&pdinv[4], g_dinv4); cudaGetSymbolAddress((void**)&pfill[4], g_fill4);
    cudaGetSymbolAddress((void**)&pscore, g_score);
    cudaGetSymbolAddress((void**)&pvals,  g_vals);
    cudaGetSymbolAddress((void**)&pwn,    g_wn);
    cudaGetSymbolAddress((void**)&pperm[0], g_perm0);
    cudaGetSymbolAddress((void**)&pperm[1], g_perm1);
    cudaGetSymbolAddress((void**)&pperm[2], g_perm2);
    cudaGetSymbolAddress((void**)&pperm[3], g_perm3);
    cudaGetSymbolAddress((void**)&pcnt,   g_cnt);
    cudaGetSymbolAddress((void**)&ptcnt,  g_tcnt);
    cudaGetSymbolAddress((void**)&pdegi,  g_degi);
    cudaGetSymbolAddress((void**)&pselfc, g_selfc);
    cudaGetSymbolAddress((void**)&pinv,   g_inv);
    cudaGetSymbolAddress((void**)&pbucket,g_bucket);

    char* base = (char*)pS;
    float* pGr   = pS;                                              // [0,16MB)
    float* pGc   = pS + 4194304;                                    // [16,32MB)
    float* ppart = pS + 8388608;                                    // [32,48MB)
    __nv_bfloat16* pA1b = (__nv_bfloat16*)(base + (size_t)48*1024*1024);  // 8MB
    __nv_bfloat16* pGrb = (__nv_bfloat16*)(base + (size_t)56*1024*1024);  // 4MB
    __nv_bfloat16* pGcb = (__nv_bfloat16*)(base + (size_t)60*1024*1024);  // 4MB

    auto g64 = [&](const float* A, const float* B, int M, int N, int K, int SK){
        dim3 g(N/64, M/64, SK);
        k_gemm_f4<64,64,8,8><<<g,64>>>(A,B,ppart,M,N,K,K/SK);
    };
    auto red = [&](float* out, int SK, int M, int N, int flags,
                   const float* dv, const float* fl, const float* bias, const float* Uin){
        size_t tot = (size_t)M*N;
        k_redepi<<<(unsigned)((tot + 255)/256), 256>>>(out, ppart, SK, M, N, flags, dv, fl, bias, Uin);
    };
    auto topk = [&](const float* x, int n, int F, const float* w, int k, int* perm){
        k_wnorm<<<1, 256>>>(w, F, pwn);
        k_score<<<(n + 255)/256, 256>>>(x, n, F, w, pwn, pscore);
        cudaMemsetAsync(ptcnt, 0, n*sizeof(int), 0);
        int chy = n/256 < 8 ? n/256 : 8;
        dim3 gr(n/256, chy);
        k_topk_cnt<<<gr, 256>>>(pscore, n, ptcnt);
        k_topk_place<<<(n + 255)/256, 256>>>(pscore, ptcnt, n, k, perm, pvals);
    };
    // dense GCN (fp32 SIMT path)
    auto gcnD = [&](const float* A, int n, const float* dv, const float* fl,
                    const float* x, int fin, const float* W, const float* b,
                    int fout, float* out, bool relu){
        if (fout <= 64 && fin <= 128){
            k_xw<<<n/8, 256>>>(x, W, pU, n, fout, fin, dv);
        } else {
            g64(x, W, n, fout, fin, 4);
            red(pU, 4, n, fout, 8, dv, nullptr, nullptr, nullptr);
        }
        g64(A, pU, n, fout, n, 16);
        red(out, 16, n, fout, 16 | (relu ? 32 : 0), dv, fl, b, pU);
    };
    // level-1 GCN via bf16 tensor cores: As1 exact in bf16, U 3-split (fp32-exact)
    auto gcnTC1 = [&](const float* x, int fin, const float* W, const float* b,
                      float* out, bool relu){
        k_xw<<<2048/8, 256>>>(x, W, pU, 2048, 64, fin, pdinv[1]);
        k_split3<<<(2048*64 + 255)/256, 256>>>(pU, pUh, pUl, pUl2, 2048*64);
        const int SK = 8, kc = 2048/SK;
        dim3 g(1, 2048/64, SK);
        k_wmma<<<g,128>>>(pA1b, pUh,  ppart, 2048, 64, 2048, kc, 0);
        k_wmma<<<g,128>>>(pA1b, pUl,  ppart, 2048, 64, 2048, kc, 1);
        k_wmma<<<g,128>>>(pA1b, pUl2, ppart, 2048, 64, 2048, kc, 1);
        red(out, SK, 2048, 64, 16 | (relu ? 32 : 0), pdinv[1], pfill[1], b, pU);
    };
    // sparse level-0 GCN
    auto gcn0 = [&](const float* x, int fin, const float* W, const float* b,
                    int fout, float* out, bool relu){
        k_xw<<<4096/8, 256>>>(x, W, pU, 4096, fout, fin, pdinv[0]);
        cudaMemsetAsync(pZ, 0, (size_t)4096*fout*sizeof(float), 0);
        k_spmm<<<(E*32 + 255)/256, 256>>>(eidx, E, pU, pZ, fout);
        int tot = 4096*fout;
        k_gcn_epi<<<(tot + 255)/256, 256>>>(pZ, pU, pdinv[0], pfill[0], b, out, 4096, fout, relu ? 1 : 0);
    };
    // pooled augment (fp32 SIMT, small levels)
    auto aug = [&](const float* Asrc, int n, const int* perm, int k, float* Adst){
        size_t rt = (size_t)k*(n/4);
        k_gather_rows<<<(unsigned)((rt + 255)/256), 256>>>(Asrc, n, perm, pGr, k);
        k_diag_r<<<(k + 255)/256, 256>>>(pGr, n, perm, k);
        size_t ct = (size_t)n*k;
        k_gather_cols<<<(unsigned)((ct + 255)/256), 256>>>(Asrc, n, perm, pGc, k);
        k_diag_c<<<(k + 255)/256, 256>>>(pGc, perm, k);
        int SK = (k >= 512) ? 4 : 8;
        g64(pGr, pGc, k, k, n, SK);
        red(Adst, SK, k, k, 4, nullptr, nullptr, nullptr, nullptr);
    };

    // ---- level-0 degrees + buckets ----
    cudaMemsetAsync(pdegi, 0, 4096*sizeof(int), 0);
    cudaMemsetAsync(pselfc, 0, 4096*sizeof(int), 0);
    k_edge_stats<<<(E + 255)/256, 256>>>(eidx, E, pdegi, pselfc);
    k_deg0_fin<<<(4096 + 255)/256, 256>>>(pdegi, pselfc, pdinv[0], pfill[0], 4096);
    cudaMemsetAsync(pcnt, 0, 4096*sizeof(int), 0);
    k_bucket_fill<<<(E + 255)/256, 256>>>(eidx, E, pcnt, pbucket);

    // ---- down level 0 (sparse) ----
    gcn0(x_in, 128, Wd[0], bd[0], 32, px0, true);

    // ---- pool to 2048; build As1 via sparse join; convert to bf16 ----
    topk(px0, 4096, 32, pv[0], 2048, pperm[0]);
    k_gather_x<<<(2048*32 + 255)/256, 256>>>(px0, 32, pperm[0], pvals, pxg, 2048);
    cudaMemsetAsync(pAs1, 0, (size_t)2048*2048*sizeof(float), 0);
    cudaMemsetAsync(pinv, 0xFF, 4096*sizeof(int), 0);
    k_set_inv<<<(2048 + 255)/256, 256>>>(pperm[0], pinv, 2048);
    k_scatter_aug_inv<<<(E + 255)/256, 256>>>(eidx, E, pinv, pAs1, 2048);
    k_join_inv<<<(E + 255)/256, 256>>>(eidx, E, pcnt, pbucket, pinv, pAs1, 2048);
    k_deg<<<(2048 + 7)/8, 256>>>(pAs1, 2048, pdinv[1], pfill[1]);
    k_f2b<<<(unsigned)(((size_t)2048*2048 + 255)/256), 256>>>(pAs1, pA1b, (size_t)2048*2048);
    gcnTC1(pxg, 32, Wd[1], bd[1], px1, true);

    // ---- level 2: pooled augment via bf16 wmma (exact: As1+I entries < 256) ----
    topk(px1, 2048, 64, pv[1], 1024, pperm[1]);
    {
        size_t rt = (size_t)1024*2048;
        k_gather_rows_bf<<<(unsigned)((rt + 255)/256), 256>>>(pAs1, 2048, pperm[1], pGrb, 1024);
        k_gather_cols_bf<<<(unsigned)((rt + 255)/256), 256>>>(pAs1, 2048, pperm[1], pGcb, 1024);
        dim3 g(1024/64, 1024/64, 1);
        k_wmma<<<g,128>>>(pGrb, pGcb, ppart, 1024, 1024, 2048, 2048, 0);
        red(pAs2, 1, 1024, 1024, 4, nullptr, nullptr, nullptr, nullptr);
    }
    k_gather_x<<<(1024*64 + 255)/256, 256>>>(px1, 64, pperm[1], pvals, pxg, 1024);
    k_deg<<<(1024 + 7)/8, 256>>>(pAs2, 1024, pdinv[2], pfill[2]);
    gcnD(pAs2, 1024, pdinv[2], pfill[2], pxg, 64, Wd[2], bd[2], 128, px2, true);

    // ---- level 3: pooled augment (512x512x1024), GCN ----
    topk(px2, 1024, 128, pv[2], 512, pperm[2]);
    aug(pAs2, 1024, pperm[2], 512, pAs3);
    k_gather_x<<<(512*128 + 255)/256, 256>>>(px2, 128, pperm[2], pvals, pxg, 512);
    k_deg<<<(512 + 7)/8, 256>>>(pAs3, 512, pdinv[3], pfill[3]);
    gcnD(pAs3, 512, pdinv[3], pfill[3], pxg, 128, Wd[3], bd[3], 256, px3, true);

    // ---- level 4: pooled augment (256x256x512), GCN ----
    topk(px3, 512, 256, pv[3], 256, pperm[3]);
    aug(pAs3, 512, pperm[3], 256, pA4);
    k_gather_x<<<(256*256 + 255)/256, 256>>>(px3, 256, pperm[3], pvals, pxg, 256);
    k_deg<<<(256 + 7)/8, 256>>>(pA4, 256, pdinv[4], pfill[4]);
    gcnD(pA4, 256, pdinv[4], pfill[4], pxg, 256, Wd[4], bd[4], 512, px4, true);

    // ---- up path ----
    k_concat_res<<<(512*512 + 255)/256, 256>>>(px3, 256, pxcat, 512);
    k_scatter_up<<<(256*256 + 255)/256, 256>>>(px4, 512, 256, pperm[3], pxcat, 256);
    gcnD(pAs3, 512, pdinv[3], pfill[3], pxcat, 512, Wu[0], bu[0], 256, pxu, true);

    k_concat_res<<<(1024*256 + 255)/256, 256>>>(px2, 128, pxcat, 1024);
    k_scatter_up<<<(512*128 + 255)/256, 256>>>(pxu, 256, 128, pperm[2], pxcat, 512);
    gcnD(pAs2, 1024, pdinv[2], pfill[2], pxcat, 256, Wu[1], bu[1], 128, pxu, true);

    k_concat_res<<<(2048*128 + 255)/256, 256>>>(px1, 64, pxcat, 2048);
    k_scatter_up<<<(1024*64 + 255)/256, 256>>>(pxu, 128, 64, pperm[1], pxcat, 1024);
    gcnTC1(pxcat, 128, Wu[2], bu[2], pxu, true);

    k_concat_res<<<(4096*64 + 255)/256, 256>>>(px0, 32, pxcat, 4096);
    k_scatter_up<<<(2048*32 + 255)/256, 256>>>(pxu, 64, 32, pperm[0], pxcat, 2048);
    gcn0(pxcat, 64, Wu[3], bu[3], 32, pxu, false);

    // ---- final GCN (sparse) + softmax ----
    gcn0(pxu, 32, Wo, bo, 37, pxcat, false);
    k_softmax<<<(4096 + 255)/256, 256>>>(pxcat, (float*)d_out, 4096, 37);
}

// round 13
// speedup vs baseline: 8.8099x; 1.0953x over previous
#include <cuda_runtime.h>
#include <cuda_bf16.h>
#include <mma.h>
#include <math.h>

using namespace nvcuda;

#define CAP 192

// ---------------- static device scratch (no allocation allowed) ----------------
__device__ float g_S[(size_t)4096*4096];      // [0,16M) Gr | [16,32M) Gc | [32,48M) part | [48,56M) A1b | [56,60M) Grb | [60,64M) Gcb
__device__ float g_As1[(size_t)2048*2048];
__device__ float g_As2[(size_t)1024*1024];
__device__ float g_As3[(size_t)512*512];
__device__ float g_A4[(size_t)256*256];
__device__ float g_x0[4096*32];
__device__ float g_x1[2048*64];
__device__ float g_x2[1024*128];
__device__ float g_x3[512*256];
__device__ float g_x4[256*512];
__device__ float g_xg[2048*64];
__device__ float g_xu[4096*64];
__device__ float g_xcat[4096*64];
__device__ float g_bU[4096*64];
__device__ float g_bZ[4096*64];
__device__ __nv_bfloat16 g_Ucat[2048*192];
__device__ float g_dinv0[4096], g_fill0[4096];
__device__ float g_dinv1[2048], g_fill1[2048];
__device__ float g_dinv2[1024], g_fill2[1024];
__device__ float g_dinv3[512],  g_fill3[512];
__device__ float g_dinv4[256],  g_fill4[256];
__device__ float g_score[4096];
__device__ int   g_perm0[2048];
__device__ int   g_perm1[1024];
__device__ int   g_perm2[512];
__device__ int   g_perm3[256];
__device__ int   g_iz[4096*3];                // degi | selfc | cnt (one memset)
__device__ int   g_tcnt[4096];
__device__ int   g_inv0[4096];
__device__ int   g_inv1[2048];
__device__ int   g_inv2[1024];
__device__ int   g_inv3[512];
__device__ int   g_bucket[4096*CAP];

// ---------------- sparse level-0 kernels ----------------

__global__ void k_edge_stats(const int* __restrict__ e, int E, int* degi, int* selfc){
    int i = blockIdx.x*blockDim.x + threadIdx.x;
    if (i >= E) return;
    int s = e[i], d = e[E+i];
    atomicAdd(&degi[d], 1);
    if (s == d) atomicAdd(&selfc[d], 1);
}

__global__ void k_deg0_fin(const int* __restrict__ degi, const int* __restrict__ selfc,
                           float* dinv, float* fill, int n){
    int i = blockIdx.x*blockDim.x + threadIdx.x;
    if (i >= n) return;
    float f = (selfc[i] == 0) ? 2.0f : 0.0f;
    float deg = (float)degi[i] + f;
    dinv[i] = (deg > 0.f) ? 1.0f/sqrtf(deg) : 0.0f;
    fill[i] = f;
}

__global__ void k_bucket_fill(const int* __restrict__ e, int E, int* cnt, int* bucket){
    int i = blockIdx.x*blockDim.x + threadIdx.x;
    if (i >= E) return;
    int s = e[i], d = e[E+i];
    if (s == d) return;
    int p = atomicAdd(&cnt[s], 1);
    if (p < CAP) bucket[s*CAP + p] = d;
}

__global__ void k_scatter_aug_inv(const int* __restrict__ e, int E, const int* __restrict__ inv,
                                  float* A, int k){
    int i = blockIdx.x*blockDim.x + threadIdx.x;
    if (i >= E) return;
    int s = e[i], d = e[E+i];
    if (s == d) return;
    int ir = inv[d], ic = inv[s];
    if (ir >= 0 && ic >= 0) atomicAdd(&A[(size_t)ir*k + ic], 2.0f);
}

__global__ void k_join_inv(const int* __restrict__ e, int E, const int* __restrict__ cnt,
                           const int* __restrict__ bucket, const int* __restrict__ inv,
                           float* A, int k){
    int i = blockIdx.x*blockDim.x + threadIdx.x;
    if (i >= E) return;
    int s2 = e[i], d2 = e[E+i];
    if (s2 == d2) return;
    int ic = inv[s2];
    if (ic < 0) return;
    int c = min(cnt[d2], CAP);
    const int* b = bucket + d2*CAP;
    for (int t = 0; t < c; t++){
        int d1 = b[t];
        if (d1 == s2) continue;
        int ir = inv[d1];
        if (ir >= 0) atomicAdd(&A[(size_t)ir*k + ic], 1.0f);
    }
}

__global__ void k_spmm(const int* __restrict__ e, int E, const float* __restrict__ U,
                       float* Z, int F){
    int w = (blockIdx.x*blockDim.x + threadIdx.x) >> 5;
    int lane = threadIdx.x & 31;
    if (w >= E) return;
    int s = e[w], d = e[E+w];
    const float* ur = U + (size_t)s*F;
    float* zr = Z + (size_t)d*F;
    for (int f = lane; f < F; f += 32) atomicAdd(&zr[f], ur[f]);
}

// ---------------- dense helpers ----------------

__global__ void k_deg(const float* __restrict__ A, int n, float* dinv, float* fill){
    int row  = blockIdx.x*(blockDim.x >> 5) + (threadIdx.x >> 5);
    int lane = threadIdx.x & 31;
    if (row >= n) return;
    const float* r = A + (size_t)row*n;
    float s = 0.f;
    for (int j = lane; j < n; j += 32) s += r[j];
    #pragma unroll
    for (int o = 16; o; o >>= 1) s += __shfl_xor_sync(0xffffffffu, s, o);
    if (lane == 0){
        float f = (r[row] == 0.0f) ? 2.0f : 0.0f;
        float deg = s + f;
        dinv[row] = (deg > 0.f) ? 1.0f/sqrtf(deg) : 0.0f;
        fill[row] = f;
    }
}

// Vectorized fp32 SIMT GEMM (no guards): M%BM==0, N%BN==0, kc%16==0
template<int BM,int BN,int TM,int TN>
__global__ void k_gemm_f4(
    const float* __restrict__ A, const float* __restrict__ B, float* __restrict__ part,
    int M, int N, int K, int kc)
{
    const int BK = 16;
    const int NT = (BM/TM)*(BN/TN);
    __shared__ float As[BK][BM+4];
    __shared__ float Bs[BK][BN];
    int tid = threadIdx.x;
    int tx = tid % (BN/TN), ty = tid / (BN/TN);
    int bm = blockIdx.y*BM, bn = blockIdx.x*BN;
    int k0 = blockIdx.z*kc;
    float acc[TM][TN] = {};
    for (int kb = k0; kb < k0 + kc; kb += BK){
        #pragma unroll
        for (int q = 0; q < (BM*4)/NT; q++){
            int idx = tid + q*NT;
            int row = idx >> 2, c4 = (idx & 3) << 2;
            float4 v = *reinterpret_cast<const float4*>(&A[(size_t)(bm+row)*K + kb + c4]);
            As[c4+0][row] = v.x; As[c4+1][row] = v.y;
            As[c4+2][row] = v.z; As[c4+3][row] = v.w;
        }
        #pragma unroll
        for (int q = 0; q < (4*BN)/NT; q++){
            int idx = tid + q*NT;
            int row = idx/(BN/4), c4 = (idx % (BN/4)) << 2;
            *reinterpret_cast<float4*>(&Bs[row][c4]) =
                *reinterpret_cast<const float4*>(&B[(size_t)(kb+row)*N + bn + c4]);
        }
        __syncthreads();
        #pragma unroll
        for (int k = 0; k < BK; k++){
            float a[TM], b[TN];
            #pragma unroll
            for (int i = 0; i < TM; i += 4)
                *reinterpret_cast<float4*>(&a[i]) = *reinterpret_cast<const float4*>(&As[k][ty*TM + i]);
            #pragma unroll
            for (int j = 0; j < TN; j += 4)
                *reinterpret_cast<float4*>(&b[j]) = *reinterpret_cast<const float4*>(&Bs[k][tx*TN + j]);
            #pragma unroll
            for (int i = 0; i < TM; i++)
                #pragma unroll
                for (int j = 0; j < TN; j++)
                    acc[i][j] += a[i]*b[j];
        }
        __syncthreads();
    }
    float* out = part + (size_t)blockIdx.z*M*N;
    #pragma unroll
    for (int i = 0; i < TM; i++){
        int gm = bm + ty*TM + i;
        #pragma unroll
        for (int j = 0; j < TN; j += 4){
            int gn = bn + tx*TN + j;
            *reinterpret_cast<float4*>(&out[(size_t)gm*N + gn]) =
                *reinterpret_cast<const float4*>(&acc[i][j]);
        }
    }
}

// bf16 WMMA GEMM (raw partials; M%64==0, N%64==0, kc%32==0)
__global__ void k_wmma(const __nv_bfloat16* __restrict__ A, const __nv_bfloat16* __restrict__ B,
                       float* __restrict__ out, int M, int N, int K, int kc)
{
    __shared__ __nv_bfloat16 As[64][40];
    __shared__ __nv_bfloat16 Bs[32][72];
    int tid = threadIdx.x;
    int warp = tid >> 5;
    int wr = warp >> 1, wc = warp & 1;
    int bm = blockIdx.y*64, bn = blockIdx.x*64;
    float* o = out + (size_t)blockIdx.z*M*N;

    wmma::fragment<wmma::accumulator, 16,16,16, float> fc[2][2];
    #pragma unroll
    for (int i = 0; i < 2; i++)
        #pragma unroll
        for (int j = 0; j < 2; j++)
            wmma::fill_fragment(fc[i][j], 0.0f);

    int k0 = blockIdx.z*kc;
    for (int kb = k0; kb < k0 + kc; kb += 32){
        #pragma unroll
        for (int q = 0; q < 2; q++){
            int idx = tid + q*128;
            int row = idx >> 2, c8 = (idx & 3) << 3;
            *reinterpret_cast<uint4*>(&As[row][c8]) =
                *reinterpret_cast<const uint4*>(&A[(size_t)(bm+row)*K + kb + c8]);
        }
        #pragma unroll
        for (int q = 0; q < 2; q++){
            int idx = tid + q*128;
            int row = idx >> 3, c8 = (idx & 7) << 3;
            *reinterpret_cast<uint4*>(&Bs[row][c8]) =
                *reinterpret_cast<const uint4*>(&B[(size_t)(kb+row)*N + bn + c8]);
        }
        __syncthreads();
        #pragma unroll
        for (int kf = 0; kf < 2; kf++){
            wmma::fragment<wmma::matrix_a, 16,16,16, __nv_bfloat16, wmma::row_major> fa[2];
            wmma::fragment<wmma::matrix_b, 16,16,16, __nv_bfloat16, wmma::row_major> fb[2];
            #pragma unroll
            for (int i = 0; i < 2; i++)
                wmma::load_matrix_sync(fa[i], &As[wr*32 + i*16][kf*16], 40);
            #pragma unroll
            for (int j = 0; j < 2; j++)
                wmma::load_matrix_sync(fb[j], &Bs[kf*16][wc*32 + j*16], 72);
            #pragma unroll
            for (int i = 0; i < 2; i++)
                #pragma unroll
                for (int j = 0; j < 2; j++)
                    wmma::mma_sync(fc[i][j], fa[i], fb[j], fc[i][j]);
        }
        __syncthreads();
    }
    #pragma unroll
    for (int i = 0; i < 2; i++)
        #pragma unroll
        for (int j = 0; j < 2; j++)
            wmma::store_matrix_sync(&o[(size_t)(bm + wr*32 + i*16)*N + bn + wc*32 + j*16],
                                    fc[i][j], N, wmma::mem_row_major);
}

// Fused skinny projection: U = dinv .* (x @ W). N<=64, K<=128, M%16==0.
// 8 warps, 2 rows/warp -> 4 accumulator chains, shared W loads per row-pair.
__global__ __launch_bounds__(256) void k_xw2(const float* __restrict__ x,
                                             const float* __restrict__ W,
                                             float* __restrict__ U,
                                             int M, int N, int K,
                                             const float* __restrict__ dinv){
    __shared__ float Ws[128][64];
    __shared__ float Xs[16][128];
    int tid = threadIdx.x;
    for (int idx = tid; idx < K*64; idx += 256){
        int k = idx >> 6, c = idx & 63;
        Ws[k][c] = (c < N) ? W[k*N + c] : 0.f;
    }
    int row0 = blockIdx.x*16;
    for (int idx = tid; idx < 16*K; idx += 256){
        int r = idx / K, k = idx - r*K;
        Xs[r][k] = x[(size_t)(row0 + r)*K + k];
    }
    __syncthreads();
    int warp = tid >> 5, lane = tid & 31;
    int r0 = warp*2, r1 = r0 + 1;
    float a00 = 0.f, a01 = 0.f, a10 = 0.f, a11 = 0.f;
    for (int k = 0; k < K; k++){
        float wa = Ws[k][lane], wb = Ws[k][lane + 32];
        float x0 = Xs[r0][k], x1 = Xs[r1][k];
        a00 += x0*wa; a01 += x0*wb;
        a10 += x1*wa; a11 += x1*wb;
    }
    int gr0 = row0 + r0, gr1 = row0 + r1;
    float d0 = dinv[gr0], d1 = dinv[gr1];
    if (lane < N){
        U[(size_t)gr0*N + lane] = d0 * a00;
        U[(size_t)gr1*N + lane] = d1 * a10;
    }
    if (lane + 32 < N){
        U[(size_t)gr0*N + lane + 32] = d0 * a01;
        U[(size_t)gr1*N + lane + 32] = d1 * a11;
    }
}

// Reduce SK partials (fixed order -> deterministic) + epilogue.
// flags: 4 zero diag, 8 scale dinv[m], 16 gcn epi, 32 relu
__global__ void k_redepi(float* out, const float* __restrict__ part, int SK, int M, int N,
                         int flags, const float* __restrict__ dinv, const float* __restrict__ fl,
                         const float* __restrict__ bias, const float* __restrict__ Uin)
{
    size_t idx = (size_t)blockIdx.x*blockDim.x + threadIdx.x;
    if (idx >= (size_t)M*N) return;
    int m = (int)(idx / N), n = (int)(idx % N);
    size_t MN = (size_t)M*N;
    float v = 0.f;
    for (int z = 0; z < SK; z++) v += part[z*MN + idx];
    if (flags & 16)      v = dinv[m]*(v + fl[m]*Uin[idx]) + bias[n];
    else if (flags & 8)  v *= dinv[m];
    if (flags & 32) v = fmaxf(v, 0.f);
    if ((flags & 4) && m == n) v = 0.f;
    out[idx] = v;
}

// Reduce for concatenated 3-split wmma: part[z][m][g*64+c], g=0..2; gcn epilogue.
__global__ void k_red3(float* out, const float* __restrict__ part, int SK, int M,
                       const float* __restrict__ dinv, const float* __restrict__ fl,
                       const float* __restrict__ bias, const float* __restrict__ Uin, int relu)
{
    int idx = blockIdx.x*blockDim.x + threadIdx.x;
    if (idx >= M*64) return;
    int m = idx >> 6, c = idx & 63;
    size_t MN = (size_t)M*192;
    float v = 0.f;
    for (int z = 0; z < SK; z++){
        const float* p = part + z*MN + (size_t)m*192;
        v += p[c] + p[64 + c] + p[128 + c];
    }
    v = dinv[m]*(v + fl[m]*Uin[idx]) + bias[c];
    if (relu) v = fmaxf(v, 0.f);
    out[idx] = v;
}

// ---------------- conversion kernels ----------------

__global__ void k_f2b(const float* __restrict__ in, __nv_bfloat16* __restrict__ out, size_t n){
    size_t i = (size_t)blockIdx.x*blockDim.x + threadIdx.x;
    if (i < n) out[i] = __float2bfloat16(in[i]);
}

// 3-term bf16 split into concatenated layout: Ucat[r][0:64)=h, [64:128)=l, [128:192)=l2
__global__ void k_split3c(const float* __restrict__ U, __nv_bfloat16* __restrict__ Ucat, int n){
    int i = blockIdx.x*blockDim.x + threadIdx.x;
    if (i >= n) return;
    int r = i >> 6, c = i & 63;
    float v = U[i];
    __nv_bfloat16 a = __float2bfloat16(v);
    float res = v - __bfloat162float(a);
    __nv_bfloat16 b = __float2bfloat16(res);
    float r2 = res - __bfloat162float(b);
    __nv_bfloat16* row = Ucat + (size_t)r*192;
    row[c] = a; row[64 + c] = b; row[128 + c] = __float2bfloat16(r2);
}

// ---------------- augment operand gathers (diag folded in) ----------------

__global__ void k_gather_rows(const float* __restrict__ A, int n, const int* __restrict__ perm,
                              float* Gr, int k){
    size_t t = (size_t)blockIdx.x*blockDim.x + threadIdx.x;
    size_t tot = (size_t)k*(n/4);
    if (t >= tot) return;
    int r = (int)(t / (n/4));
    int c4 = (int)(t % (n/4))*4;
    int pr = perm[r];
    float4 v = *reinterpret_cast<const float4*>(&A[(size_t)pr*n + c4]);
    if (pr >= c4 && pr < c4 + 4) (&v.x)[pr - c4] += 1.0f;
    *reinterpret_cast<float4*>(&Gr[(size_t)r*n + c4]) = v;
}
__global__ void k_gather_cols(const float* __restrict__ A, int n, const int* __restrict__ perm,
                              float* Gc, int k){
    size_t t = (size_t)blockIdx.x*blockDim.x + threadIdx.x;
    if (t >= (size_t)n*k) return;
    int j = (int)(t / k), c = (int)(t % k);
    int pc = perm[c];
    Gc[t] = A[(size_t)j*n + pc] + ((j == pc) ? 1.f : 0.f);
}

// bf16 versions with +I folded in
__global__ void k_gather_rows_bf(const float* __restrict__ A, int n, const int* __restrict__ perm,
                                 __nv_bfloat16* Gr, int k){
    size_t t = (size_t)blockIdx.x*blockDim.x + threadIdx.x;
    if (t >= (size_t)k*n) return;
    int r = (int)(t / n), c = (int)(t % n);
    int pr = perm[r];
    float v = A[(size_t)pr*n + c] + ((c == pr) ? 1.f : 0.f);
    Gr[t] = __float2bfloat16(v);
}
__global__ void k_gather_cols_bf(const float* __restrict__ A, int n, const int* __restrict__ perm,
                                 __nv_bfloat16* Gc, int k){
    size_t t = (size_t)blockIdx.x*blockDim.x + threadIdx.x;
    if (t >= (size_t)n*k) return;
    int j = (int)(t / k), c = (int)(t % k);
    int pc = perm[c];
    float v = A[(size_t)j*n + pc] + ((j == pc) ? 1.f : 0.f);
    Gc[t] = __float2bfloat16(v);
}

// ---------------- gcn epilogue (sparse path) ----------------

__global__ void k_gcn_epi(const float* Z, const float* U, const float* dinv, const float* fill,
                          const float* __restrict__ b, float* out, int n, int F, int relu){
    int idx = blockIdx.x*blockDim.x + threadIdx.x;
    if (idx >= n*F) return;
    int i = idx / F, f = idx % F;
    float v = dinv[i]*(Z[idx] + fill[i]*U[idx]) + b[f];
    if (relu) v = fmaxf(v, 0.f);
    out[idx] = v;
}

// ---------------- topk / unpool / misc ----------------

// fused ||w|| + score (each block recomputes the tiny norm)
__global__ void k_score(const float* __restrict__ x, int n, int F,
                        const float* __restrict__ w, float* score){
    __shared__ float ws[256];
    __shared__ float sh[256];
    int tid = threadIdx.x;
    float wv = (tid < F) ? w[tid] : 0.f;
    ws[tid] = wv;
    sh[tid] = wv*wv;
    __syncthreads();
    for (int o = 128; o; o >>= 1){
        if (tid < o) sh[tid] += sh[tid + o];
        __syncthreads();
    }
    float inv_nrm = 1.0f / sqrtf(sh[0]);
    int i = blockIdx.x*256 + tid;
    if (i >= n) return;
    const float* r = x + (size_t)i*F;
    float s = 0.f;
    for (int f = 0; f < F; f++) s += r[f]*ws[f];
    score[i] = tanhf(s * inv_nrm);
}

__global__ void k_topk_cnt(const float* __restrict__ s, int n, int* cnt){
    __shared__ float sj[256];
    int i = blockIdx.x*256 + threadIdx.x;
    float si = s[i];
    int chunk = n / gridDim.y;
    int j0 = blockIdx.y * chunk;
    int c = 0;
    for (int jb = j0; jb < j0 + chunk; jb += 256){
        sj[threadIdx.x] = s[jb + threadIdx.x];
        __syncthreads();
        #pragma unroll 8
        for (int t = 0; t < 256; t++){
            float v = sj[t]; int j = jb + t;
            c += (v > si) || (v == si && j < i);
        }
        __syncthreads();
    }
    atomicAdd(&cnt[i], c);
}

// fused: place perm + inverse perm + gathered/scaled features (warp per node)
__global__ void k_topk_fin(const float* __restrict__ s, const int* __restrict__ cnt,
                           const float* __restrict__ x, int F, int n, int k,
                           int* perm, int* inv, float* xg){
    int node = (blockIdx.x*blockDim.x + threadIdx.x) >> 5;
    int lane = threadIdx.x & 31;
    if (node >= n) return;
    int c = cnt[node];
    bool keep = c < k;
    if (lane == 0){
        if (keep) perm[c] = node;
        inv[node] = keep ? c : -1;
    }
    if (!keep) return;
    float sv = tanhf(1.f) == 0.f ? 0.f : s[node]; // keep s read after cnt (no aliasing anyway)
    sv = s[node];
    const float* xr = x + (size_t)node*F;
    float* o = xg + (size_t)c*F;
    for (int f = lane; f < F; f += 32) o[f] = xr[f]*sv;
}

// fused unpool: out[i][f] = f<C ? res[i][f] : (inv[i]>=0 ? xprev[inv[i]][f-C] : 0)
__global__ void k_unpool(const float* __restrict__ res, int C,
                         const float* __restrict__ xprev, int Fx,
                         const int* __restrict__ inv, float* out, int n){
    int t = blockIdx.x*blockDim.x + threadIdx.x;
    int W = 2*C;
    if (t >= n*W) return;
    int r = t / W, f = t % W;
    float v;
    if (f < C) v = res[(size_t)r*C + f];
    else {
        int j = inv[r];
        v = (j >= 0) ? xprev[(size_t)j*Fx + (f - C)] : 0.f;
    }
    out[t] = v;
}

__global__ void k_softmax(const float* z, float* out, int n, int C){
    int i = blockIdx.x*blockDim.x + threadIdx.x;
    if (i >= n) return;
    const float* r = z + (size_t)i*C;
    float m = -1e30f;
    for (int c = 0; c < C; c++) m = fmaxf(m, r[c]);
    float s = 0.f;
    for (int c = 0; c < C; c++) s += expf(r[c] - m);
    float inv = 1.0f/s;
    for (int c = 0; c < C; c++) out[(size_t)i*C + c] = expf(r[c] - m)*inv;
}

// ---------------- host orchestration ----------------

extern "C" void kernel_launch(void* const* d_in, const int* in_sizes, int n_in,
                              void* d_out, int out_size){
    const float* x_in = (const float*)d_in[0];
    const int*   eidx = (const int*)d_in[1];
    const float *Wd[5], *bd[5], *pv[4], *Wu[4], *bu[4];
    for (int i = 0; i < 5; i++){ Wd[i] = (const float*)d_in[2 + 2*i]; bd[i] = (const float*)d_in[3 + 2*i]; }
    for (int i = 0; i < 4; i++)  pv[i] = (const float*)d_in[12 + i];
    for (int i = 0; i < 4; i++){ Wu[i] = (const float*)d_in[16 + 2*i]; bu[i] = (const float*)d_in[17 + 2*i]; }
    const float* Wo = (const float*)d_in[24];
    const float* bo = (const float*)d_in[25];
    int E = in_sizes[1] / 2;

    float *pS,*pAs1,*pAs2,*pAs3,*pA4;
    float *px0,*px1,*px2,*px3,*px4,*pxg,*pxu,*pxcat,*pU,*pZ;
    float *pscore;
    float *pdinv[5], *pfill[5];
    __nv_bfloat16 *pUcat;
    int *pperm[4],*pinvl[4],*piz,*ptcnt,*pbucket;
    cudaGetSymbolAddress((void**)&pS,    g_S);
    cudaGetSymbolAddress((void**)&pAs1,  g_As1);
    cudaGetSymbolAddress((void**)&pAs2,  g_As2);
    cudaGetSymbolAddress((void**)&pAs3,  g_As3);
    cudaGetSymbolAddress((void**)&pA4,   g_A4);
    cudaGetSymbolAddress((void**)&px0,   g_x0);
    cudaGetSymbolAddress((void**)&px1,   g_x1);
    cudaGetSymbolAddress((void**)&px2,   g_x2);
    cudaGetSymbolAddress((void**)&px3,   g_x3);
    cudaGetSymbolAddress((void**)&px4,   g_x4);
    cudaGetSymbolAddress((void**)&pxg,   g_xg);
    cudaGetSymbolAddress((void**)&pxu,   g_xu);
    cudaGetSymbolAddress((void**)&pxcat, g_xcat);
    cudaGetSymbolAddress((void**)&pU,    g_bU);
    cudaGetSymbolAddress((void**)&pZ,    g_bZ);
    cudaGetSymbolAddress((void**)&pUcat, g_Ucat);
    cudaGetSymbolAddress((void**)&pdinv[0], g_dinv0); cudaGetSymbolAddress((void**)&pfill[0], g_fill0);
    cudaGetSymbolAddress((void**)&pdinv[1], g_dinv1); cudaGetSymbolAddress((void**)&pfill[1], g_fill1);
    cudaGetSymbolAddress((void**)&pdinv[2], g_dinv2); cudaGetSymbolAddress((void**)&pfill[2], g_fill2);
    cudaGetSymbolAddress((void**)&pdinv[3], g_dinv3); cudaGetSymbolAddress((void**)&pfill[3], g_fill3);
    cudaGetSymbolAddress((void**)&pdinv[4], g_dinv4); cudaGetSymbolAddress((void**)&pfill[4], g_fill4);
    cudaGetSymbolAddress((void**)&pscore, g_score);
    cudaGetSymbolAddress((void**)&pperm[0], g_perm0);
    cudaGetSymbolAddress((void**)&pperm[1], g_perm1);
    cudaGetSymbolAddress((void**)&pperm[2], g_perm2);
    cudaGetSymbolAddress((void**)&pperm[3], g_perm3);
    cudaGetSymbolAddress((void**)&pinvl[0], g_inv0);
    cudaGetSymbolAddress((void**)&pinvl[1], g_inv1);
    cudaGetSymbolAddress((void**)&pinvl[2], g_inv2);
    cudaGetSymbolAddress((void**)&pinvl[3], g_inv3);
    cudaGetSymbolAddress((void**)&piz,    g_iz);
    cudaGetSymbolAddress((void**)&ptcnt,  g_tcnt);
    cudaGetSymbolAddress((void**)&pbucket,g_bucket);
    int* pdegi  = piz;
    int* pselfc = piz + 4096;
    int* pcnt   = piz + 8192;

    char* base = (char*)pS;
    float* pGr   = pS;
    float* pGc   = pS + 4194304;
    float* ppart = pS + 8388608;
    __nv_bfloat16* pA1b = (__nv_bfloat16*)(base + (size_t)48*1024*1024);
    __nv_bfloat16* pGrb = (__nv_bfloat16*)(base + (size_t)56*1024*1024);
    __nv_bfloat16* pGcb = (__nv_bfloat16*)(base + (size_t)60*1024*1024);

    auto g64 = [&](const float* A, const float* B, int M, int N, int K, int SK){
        dim3 g(N/64, M/64, SK);
        k_gemm_f4<64,64,8,8><<<g,64>>>(A,B,ppart,M,N,K,K/SK);
    };
    auto red = [&](float* out, int SK, int M, int N, int flags,
                   const float* dv, const float* fl, const float* bias, const float* Uin){
        size_t tot = (size_t)M*N;
        k_redepi<<<(unsigned)((tot + 255)/256), 256>>>(out, ppart, SK, M, N, flags, dv, fl, bias, Uin);
    };
    auto topk = [&](const float* x, int n, int F, const float* w, int k, int lvl, float* xg){
        k_score<<<(n + 255)/256, 256>>>(x, n, F, w, pscore);
        cudaMemsetAsync(ptcnt, 0, n*sizeof(int), 0);
        int chy = n/256 < 8 ? n/256 : 8;
        dim3 gr(n/256, chy);
        k_topk_cnt<<<gr, 256>>>(pscore, n, ptcnt);
        k_topk_fin<<<(n*32 + 255)/256, 256>>>(pscore, ptcnt, x, F, n, k, pperm[lvl], pinvl[lvl], xg);
    };
    auto gcnD = [&](const float* A, int n, const float* dv, const float* fl,
                    const float* x, int fin, const float* W, const float* b,
                    int fout, float* out, bool relu){
        if (fout <= 64 && fin <= 128){
            k_xw2<<<n/16, 256>>>(x, W, pU, n, fout, fin, dv);
        } else {
            g64(x, W, n, fout, fin, 4);
            red(pU, 4, n, fout, 8, dv, nullptr, nullptr, nullptr);
        }
        g64(A, pU, n, fout, n, 16);
        red(out, 16, n, fout, 16 | (relu ? 32 : 0), dv, fl, b, pU);
    };
    // level-1 GCN via bf16 TC: As1 exact bf16, U 3-split concatenated (fp32-exact), one wmma
    auto gcnTC1 = [&](const float* x, int fin, const float* W, const float* b,
                      float* out, bool relu){
        k_xw2<<<2048/16, 256>>>(x, W, pU, 2048, 64, fin, pdinv[1]);
        k_split3c<<<(2048*64 + 255)/256, 256>>>(pU, pUcat, 2048*64);
        const int SK = 8;
        dim3 g(3, 2048/64, SK);
        k_wmma<<<g,128>>>(pA1b, pUcat, ppart, 2048, 192, 2048, 2048/SK);
        k_red3<<<(2048*64 + 255)/256, 256>>>(out, ppart, SK, 2048, pdinv[1], pfill[1], b, pU, relu ? 1 : 0);
    };
    auto gcn0 = [&](const float* x, int fin, const float* W, const float* b,
                    int fout, float* out, bool relu){
        k_xw2<<<4096/16, 256>>>(x, W, pU, 4096, fout, fin, pdinv[0]);
        cudaMemsetAsync(pZ, 0, (size_t)4096*fout*sizeof(float), 0);
        k_spmm<<<(E*32 + 255)/256, 256>>>(eidx, E, pU, pZ, fout);
        int tot = 4096*fout;
        k_gcn_epi<<<(tot + 255)/256, 256>>>(pZ, pU, pdinv[0], pfill[0], b, out, 4096, fout, relu ? 1 : 0);
    };
    auto aug = [&](const float* Asrc, int n, const int* perm, int k, float* Adst){
        size_t rt = (size_t)k*(n/4);
        k_gather_rows<<<(unsigned)((rt + 255)/256), 256>>>(Asrc, n, perm, pGr, k);
        size_t ct = (size_t)n*k;
        k_gather_cols<<<(unsigned)((ct + 255)/256), 256>>>(Asrc, n, perm, pGc, k);
        int SK = (k >= 512) ? 4 : 8;
        g64(pGr, pGc, k, k, n, SK);
        red(Adst, SK, k, k, 4, nullptr, nullptr, nullptr, nullptr);
    };

    // ---- level-0 degrees + buckets ----
    cudaMemsetAsync(piz, 0, 3*4096*sizeof(int), 0);
    k_edge_stats<<<(E + 255)/256, 256>>>(eidx, E, pdegi, pselfc);
    k_deg0_fin<<<(4096 + 255)/256, 256>>>(pdegi, pselfc, pdinv[0], pfill[0], 4096);
    k_bucket_fill<<<(E + 255)/256, 256>>>(eidx, E, pcnt, pbucket);

    // ---- down level 0 (sparse) ----
    gcn0(x_in, 128, Wd[0], bd[0], 32, px0, true);

    // ---- pool to 2048; build As1 via sparse join; bf16 ----
    topk(px0, 4096, 32, pv[0], 2048, 0, pxg);
    cudaMemsetAsync(pAs1, 0, (size_t)2048*2048*sizeof(float), 0);
    k_scatter_aug_inv<<<(E + 255)/256, 256>>>(eidx, E, pinvl[0], pAs1, 2048);
    k_join_inv<<<(E + 255)/256, 256>>>(eidx, E, pcnt, pbucket, pinvl[0], pAs1, 2048);
    k_deg<<<(2048 + 7)/8, 256>>>(pAs1, 2048, pdinv[1], pfill[1]);
    k_f2b<<<(unsigned)(((size_t)2048*2048 + 255)/256), 256>>>(pAs1, pA1b, (size_t)2048*2048);
    gcnTC1(pxg, 32, Wd[1], bd[1], px1, true);

    // ---- level 2: pooled augment via bf16 wmma ----
    topk(px1, 2048, 64, pv[1], 1024, 1, pxg);
    {
        size_t rt = (size_t)1024*2048;
        k_gather_rows_bf<<<(unsigned)((rt + 255)/256), 256>>>(pAs1, 2048, pperm[1], pGrb, 1024);
        k_gather_cols_bf<<<(unsigned)((rt + 255)/256), 256>>>(pAs1, 2048, pperm[1], pGcb, 1024);
        dim3 g(1024/64, 1024/64, 2);
        k_wmma<<<g,128>>>(pGrb, pGcb, ppart, 1024, 1024, 2048, 1024);
        red(pAs2, 2, 1024, 1024, 4, nullptr, nullptr, nullptr, nullptr);
    }
    k_deg<<<(1024 + 7)/8, 256>>>(pAs2, 1024, pdinv[2], pfill[2]);
    gcnD(pAs2, 1024, pdinv[2], pfill[2], pxg, 64, Wd[2], bd[2], 128, px2, true);

    // ---- level 3 ----
    topk(px2, 1024, 128, pv[2], 512, 2, pxg);
    aug(pAs2, 1024, pperm[2], 512, pAs3);
    k_deg<<<(512 + 7)/8, 256>>>(pAs3, 512, pdinv[3], pfill[3]);
    gcnD(pAs3, 512, pdinv[3], pfill[3], pxg, 128, Wd[3], bd[3], 256, px3, true);

    // ---- level 4 ----
    topk(px3, 512, 256, pv[3], 256, 3, pxg);
    aug(pAs3, 512, pperm[3], 256, pA4);
    k_deg<<<(256 + 7)/8, 256>>>(pA4, 256, pdinv[4], pfill[4]);
    gcnD(pA4, 256, pdinv[4], pfill[4], pxg, 256, Wd[4], bd[4], 512, px4, true);

    // ---- up path (fused unpool) ----
    k_unpool<<<(512*512 + 255)/256, 256>>>(px3, 256, px4, 512, pinvl[3], pxcat, 512);
    gcnD(pAs3, 512, pdinv[3], pfill[3], pxcat, 512, Wu[0], bu[0], 256, pxu, true);

    k_unpool<<<(1024*256 + 255)/256, 256>>>(px2, 128, pxu, 256, pinvl[2], pxcat, 1024);
    gcnD(pAs2, 1024, pdinv[2], pfill[2], pxcat, 256, Wu[1], bu[1], 128, pxu, true);

    k_unpool<<<(2048*128 + 255)/256, 256>>>(px1, 64, pxu, 128, pinvl[1], pxcat, 2048);
    gcnTC1(pxcat, 128, Wu[2], bu[2], pxu, true);

    k_unpool<<<(4096*64 + 255)/256, 256>>>(px0, 32, pxu, 64, pinvl[0], pxcat, 4096);
    gcn0(pxcat, 64, Wu[3], bu[3], 32, pxu, false);

    // ---- final GCN (sparse) + softmax ----
    gcn0(pxu, 32, Wo, bo, 37, pxcat, false);
    k_softmax<<<(4096 + 255)/256, 256>>>(pxcat, (float*)d_out, 4096, 37);
}